// round 14
// baseline (speedup 1.0000x reference)
#include <cuda_runtime.h>
#include <cuda_fp16.h>
#include <cstdint>
#include <math.h>

// ---------------- problem constants ----------------
#define DIMN 768
#define NL   13
#define NH   12
#define HD   64
#define VOCAB 50257
#define SEQ  512
#define BATCH 4
#define HID  3072
#define BT   (BATCH*SEQ)      // 2048
#define QKVW (3*DIMN)         // 2304

// ---------------- gemm config ----------------
#define SM_DENSE (2 * 4 * 10240)   // 81920
#define SM_GHOST (2 * 3 * 18432)   // 110592
#define SM_HEAD  (2 * 2 * 18432)   // 73728

// ---------------- flash attention config ----------------
#define QT 64
#define KT 64
#define APAD 65
#define SM_ATTN (4 * QT * APAD * 4)  // 66560 bytes

// ---------------- scratch ----------------
__device__ float  g_x   [(size_t)BT*DIMN];
__device__ float  g_qkv [(size_t)BT*QKVW];
__device__ float  g_s0_ln [BT];
__device__ float  g_s0_mlp[BT];
__device__ __half g_ln_hi [(size_t)BT*DIMN];
__device__ __half g_ln_lo [(size_t)BT*DIMN];
__device__ __half g_att_hi[(size_t)BT*DIMN];
__device__ __half g_att_lo[(size_t)BT*DIMN];
__device__ __half g_mlp_hi[(size_t)BT*HID];
__device__ __half g_mlp_lo[(size_t)BT*HID];
__device__ __half w_qkv_hi [(size_t)NL*QKVW*DIMN];
__device__ __half w_qkv_lo [(size_t)NL*QKVW*DIMN];
__device__ __half w_proj_hi[(size_t)NL*DIMN*DIMN];
__device__ __half w_proj_lo[(size_t)NL*DIMN*DIMN];
__device__ __half w_mlp1_i [(size_t)NL*HID*DIMN];
__device__ __half w_mlp2_i [(size_t)NL*DIMN*HID];
__device__ __half w_head_i [(size_t)VOCAB*DIMN];

// ---------------- helpers ----------------
__device__ __forceinline__ void split1(float v, __half& h, __half& l) {
    h = __float2half_rn(v);
    l = __float2half_rn(v - __half2float(h));
}
__device__ __forceinline__ float gelu_tanh(float x) {
    float x3 = x * x * x;
    return 0.5f * x * (1.0f + tanhf(0.7978845608028654f * (x + 0.044715f * x3)));
}
__device__ __forceinline__ uint32_t smem_u32(const void* p) {
    uint32_t a;
    asm("{ .reg .u64 t; cvta.to.shared.u64 t, %1; cvt.u32.u64 %0, t; }" : "=r"(a) : "l"(p));
    return a;
}
__device__ __forceinline__ void cp16(uint32_t dst, const void* src) {
    asm volatile("cp.async.cg.shared.global [%0], [%1], 16;" :: "r"(dst), "l"(src));
}
#define CP_COMMIT() asm volatile("cp.async.commit_group;" ::: "memory")
#define CP_WAIT1()  asm volatile("cp.async.wait_group 1;" ::: "memory")
#define CP_WAIT0()  asm volatile("cp.async.wait_group 0;" ::: "memory")

#define LDSM4(r0, r1, r2, r3, addr)                                           \
    asm volatile("ldmatrix.sync.aligned.m8n8.x4.shared.b16 {%0,%1,%2,%3}, [%4];" \
        : "=r"(r0), "=r"(r1), "=r"(r2), "=r"(r3) : "r"(addr))

#define MMA16816(c, a0, a1, a2, a3, b0, b1)                                   \
    asm volatile(                                                             \
        "mma.sync.aligned.m16n8k16.row.col.f32.f16.f16.f32 "                  \
        "{%0,%1,%2,%3}, {%4,%5,%6,%7}, {%8,%9}, {%0,%1,%2,%3};"               \
        : "+f"((c)[0]), "+f"((c)[1]), "+f"((c)[2]), "+f"((c)[3])              \
        : "r"(a0), "r"(a1), "r"(a2), "r"(a3), "r"(b0), "r"(b1))

// warp+block reduce: 256 threads, result broadcast to all
__device__ __forceinline__ float blk_sum(float v, float* sred, int tid) {
    #pragma unroll
    for (int o = 16; o > 0; o >>= 1) v += __shfl_xor_sync(0xffffffffu, v, o);
    if ((tid & 31) == 0) sred[tid >> 5] = v;
    __syncthreads();
    float t = sred[0] + sred[1] + sred[2] + sred[3]
            + sred[4] + sred[5] + sred[6] + sred[7];
    __syncthreads();
    return t;
}

// ---------------- merged conversion kernel ----------------
#define N0 ((size_t)NL*QKVW*DIMN)
#define N1 ((size_t)NL*DIMN*DIMN)
#define N2 ((size_t)NL*HID*DIMN)
#define N3 ((size_t)NL*DIMN*HID)
#define N4 ((size_t)VOCAB*DIMN)
#define NB0 ((unsigned)(N0/1024))
#define NB1 ((unsigned)(N1/1024))
#define NB2 ((unsigned)(N2/2048))
#define NB3 ((unsigned)(N3/2048))
#define NB4 ((unsigned)((N4+2047)/2048))

__device__ __forceinline__ void conv_w_body(const float* __restrict__ w,
                                            __half* __restrict__ hi, __half* __restrict__ lo,
                                            size_t n, unsigned blk) {
    size_t i = ((size_t)blk * 256 + threadIdx.x) * 4;
    if (i >= n) return;
    float4 v = *(const float4*)(w + i);
    __half h[4], l[4];
    split1(v.x, h[0], l[0]); split1(v.y, h[1], l[1]);
    split1(v.z, h[2], l[2]); split1(v.w, h[3], l[3]);
    *(ushort4*)(hi + i) = make_ushort4(__half_as_ushort(h[0]), __half_as_ushort(h[1]),
                                       __half_as_ushort(h[2]), __half_as_ushort(h[3]));
    *(ushort4*)(lo + i) = make_ushort4(__half_as_ushort(l[0]), __half_as_ushort(l[1]),
                                       __half_as_ushort(l[2]), __half_as_ushort(l[3]));
}
__device__ __forceinline__ void conv_i_body(const int* __restrict__ idx,
                                            __half* __restrict__ o, size_t n, unsigned blk) {
    size_t i = ((size_t)blk * 256 + threadIdx.x) * 8;
    if (i >= n) return;
    int4 a = *(const int4*)(idx + i);
    int4 b = *(const int4*)(idx + i + 4);
    int id[8] = {a.x, a.y, a.z, a.w, b.x, b.y, b.z, b.w};
    ushort h[8];
    #pragma unroll
    for (int j = 0; j < 8; j++)
        h[j] = __half_as_ushort(__float2half_rn((float)id[j]));
    *(uint4*)(o + i) = *(uint4*)h;
}

__global__ void conv_all(const float* __restrict__ in_w,  const float* __restrict__ out_w,
                         const int* __restrict__ i1, const int* __restrict__ i2,
                         const int* __restrict__ ih,
                         __half* __restrict__ wq_hi_, __half* __restrict__ wq_lo_,
                         __half* __restrict__ wp_hi_, __half* __restrict__ wp_lo_,
                         __half* __restrict__ w1_, __half* __restrict__ w2_,
                         __half* __restrict__ wh_) {
    unsigned b = blockIdx.x;
    if (b < NB0) { conv_w_body(in_w,  wq_hi_, wq_lo_, N0, b); return; }
    b -= NB0;
    if (b < NB1) { conv_w_body(out_w, wp_hi_, wp_lo_, N1, b); return; }
    b -= NB1;
    if (b < NB2) { conv_i_body(i1, w1_, N2, b); return; }
    b -= NB2;
    if (b < NB3) { conv_i_body(i2, w2_, N3, b); return; }
    b -= NB3;
    conv_i_body(ih, wh_, N4, b);
}

// ---------------- embedding ----------------
__global__ void embed_kernel(const int* __restrict__ idx, const float* __restrict__ tok,
                             const float* __restrict__ pos, float* __restrict__ x) {
    int r = blockIdx.x;
    int t = r % SEQ;
    int token = idx[r];
    const float* tr = tok + (size_t)token * DIMN;
    const float* pr = pos + (size_t)t * DIMN;
    float* xr = x + (size_t)r * DIMN;
    for (int d = threadIdx.x; d < DIMN; d += blockDim.x)
        xr[d] = tr[d] + pr[d];
}

// ---------------- layernorm -> split planes + rowsum (shuffle reductions) ----------------
__global__ void ln_kernel(const float* __restrict__ x, const float* __restrict__ g,
                          const float* __restrict__ b,
                          __half* __restrict__ ohi, __half* __restrict__ olo,
                          float* __restrict__ s0) {
    int r = blockIdx.x;
    int tid = threadIdx.x;
    const float* xr = x + (size_t)r * DIMN;
    __shared__ float sred[8];

    float v0 = xr[tid], v1 = xr[tid + 256], v2 = xr[tid + 512];
    float mean = blk_sum(v0 + v1 + v2, sred, tid) * (1.0f / DIMN);
    float d0 = v0 - mean, d1 = v1 - mean, d2 = v2 - mean;
    float var = blk_sum(d0 * d0 + d1 * d1 + d2 * d2, sred, tid) * (1.0f / DIMN);
    float inv = rsqrtf(var + 1e-5f);
    float o0 = d0 * inv * g[tid]       + b[tid];
    float o1 = d1 * inv * g[tid + 256] + b[tid + 256];
    float o2 = d2 * inv * g[tid + 512] + b[tid + 512];
    float tot = blk_sum(o0 + o1 + o2, sred, tid);
    if (tid == 0) s0[r] = tot;
    __half h, l;
    size_t base = (size_t)r * DIMN;
    split1(o0, h, l); ohi[base + tid]       = h; olo[base + tid]       = l;
    split1(o1, h, l); ohi[base + tid + 256] = h; olo[base + tid + 256] = l;
    split1(o2, h, l); ohi[base + tid + 512] = h; olo[base + tid + 512] = l;
}

// ---------------- rowsum of split planes (shuffle) ----------------
__global__ void rowsum_kernel(const __half* __restrict__ hi, const __half* __restrict__ lo,
                              float* __restrict__ s0, int K) {
    int r = blockIdx.x;
    int tid = threadIdx.x;
    __shared__ float sred[8];
    float s = 0.f;
    for (int k = tid * 4; k < K; k += 1024) {
        float2 h2 = __half22float2(*(const __half2*)(hi + (size_t)r * K + k));
        float2 h3 = __half22float2(*(const __half2*)(hi + (size_t)r * K + k + 2));
        float2 l2 = __half22float2(*(const __half2*)(lo + (size_t)r * K + k));
        float2 l3 = __half22float2(*(const __half2*)(lo + (size_t)r * K + k + 2));
        s += h2.x + h2.y + h3.x + h3.y + l2.x + l2.y + l3.x + l3.y;
    }
    float tot = blk_sum(s, sred, tid);
    if (tid == 0) s0[r] = tot;
}

// ---------------- flash attention ----------------
__global__ void __launch_bounds__(256)
flash_attn(const float* __restrict__ qkv,
           __half* __restrict__ ohi, __half* __restrict__ olo) {
    extern __shared__ float smf[];
    float* Qs = smf;
    float* Ks = Qs + QT * APAD;
    float* Vs = Ks + KT * APAD;
    float* Ps = Vs + KT * APAD;

    int qt = blockIdx.x, h = blockIdx.y, b = blockIdx.z;
    int tid = threadIdx.x;
    int ty = tid >> 4, tx = tid & 15;
    int q0 = qt * QT;

    for (int i = tid; i < QT * 16; i += 256) {
        int r = i >> 4, c4 = (i & 15) * 4;
        const float* src = qkv + ((size_t)(b * SEQ + q0 + r)) * QKVW + h * HD + c4;
        float4 v = *(const float4*)src;
        float* dst = Qs + r * APAD + c4;
        dst[0] = v.x * 0.125f; dst[1] = v.y * 0.125f;
        dst[2] = v.z * 0.125f; dst[3] = v.w * 0.125f;
    }

    float m[4], l[4], O[4][4];
    #pragma unroll
    for (int i = 0; i < 4; i++) {
        m[i] = -1e30f; l[i] = 0.f;
        #pragma unroll
        for (int j = 0; j < 4; j++) O[i][j] = 0.f;
    }
    __syncthreads();

    for (int kt = 0; kt <= qt; kt++) {
        int k0 = kt * KT;
        for (int i = tid; i < KT * 16; i += 256) {
            int r = i >> 4, c4 = (i & 15) * 4;
            size_t rowb = ((size_t)(b * SEQ + k0 + r)) * QKVW + h * HD + c4;
            float4 kv = *(const float4*)(qkv + rowb + DIMN);
            float* kd = Ks + r * APAD + c4;
            kd[0] = kv.x; kd[1] = kv.y; kd[2] = kv.z; kd[3] = kv.w;
            float4 vv = *(const float4*)(qkv + rowb + 2 * DIMN);
            float* vd = Vs + r * APAD + c4;
            vd[0] = vv.x; vd[1] = vv.y; vd[2] = vv.z; vd[3] = vv.w;
        }
        __syncthreads();

        float s[4][4];
        #pragma unroll
        for (int i = 0; i < 4; i++)
            #pragma unroll
            for (int j = 0; j < 4; j++) s[i][j] = 0.f;
        #pragma unroll 8
        for (int d = 0; d < HD; d++) {
            float qv[4], kv[4];
            #pragma unroll
            for (int i = 0; i < 4; i++) qv[i] = Qs[(ty * 4 + i) * APAD + d];
            #pragma unroll
            for (int j = 0; j < 4; j++) kv[j] = Ks[(tx * 4 + j) * APAD + d];
            #pragma unroll
            for (int i = 0; i < 4; i++)
                #pragma unroll
                for (int j = 0; j < 4; j++) s[i][j] = fmaf(qv[i], kv[j], s[i][j]);
        }
        if (kt == qt) {
            #pragma unroll
            for (int i = 0; i < 4; i++)
                #pragma unroll
                for (int j = 0; j < 4; j++)
                    if (k0 + tx * 4 + j > q0 + ty * 4 + i) s[i][j] = -1e30f;
        }

        float mt[4];
        #pragma unroll
        for (int i = 0; i < 4; i++)
            mt[i] = fmaxf(fmaxf(s[i][0], s[i][1]), fmaxf(s[i][2], s[i][3]));
        #pragma unroll
        for (int o = 1; o < 16; o <<= 1)
            #pragma unroll
            for (int i = 0; i < 4; i++)
                mt[i] = fmaxf(mt[i], __shfl_xor_sync(0xffffffffu, mt[i], o));

        float ps[4];
        #pragma unroll
        for (int i = 0; i < 4; i++) {
            float mn = fmaxf(m[i], mt[i]);
            float sc = __expf(m[i] - mn);
            m[i] = mn;
            l[i] *= sc;
            float psum = 0.f;
            #pragma unroll
            for (int j = 0; j < 4; j++) {
                float p = __expf(s[i][j] - mn);
                Ps[(ty * 4 + i) * APAD + tx * 4 + j] = p;
                psum += p;
            }
            ps[i] = psum;
            #pragma unroll
            for (int j = 0; j < 4; j++) O[i][j] *= sc;
        }
        #pragma unroll
        for (int o = 1; o < 16; o <<= 1)
            #pragma unroll
            for (int i = 0; i < 4; i++)
                ps[i] += __shfl_xor_sync(0xffffffffu, ps[i], o);
        #pragma unroll
        for (int i = 0; i < 4; i++) l[i] += ps[i];
        __syncthreads();

        #pragma unroll 8
        for (int k = 0; k < KT; k++) {
            float pv[4], vv[4];
            #pragma unroll
            for (int i = 0; i < 4; i++) pv[i] = Ps[(ty * 4 + i) * APAD + k];
            #pragma unroll
            for (int j = 0; j < 4; j++) vv[j] = Vs[k * APAD + tx * 4 + j];
            #pragma unroll
            for (int i = 0; i < 4; i++)
                #pragma unroll
                for (int j = 0; j < 4; j++) O[i][j] = fmaf(pv[i], vv[j], O[i][j]);
        }
        __syncthreads();
    }

    #pragma unroll
    for (int i = 0; i < 4; i++) {
        float inv = 1.0f / l[i];
        size_t base = ((size_t)(b * SEQ + q0 + ty * 4 + i)) * DIMN + h * HD + tx * 4;
        #pragma unroll
        for (int j = 0; j < 4; j++) {
            float val = O[i][j] * inv;
            __half hh, ll; split1(val, hh, ll);
            ohi[base + j] = hh; olo[base + j] = ll;
        }
    }
}

// ---------------- HMMA GEMM ----------------
// GHOST,ALO select term structure:
//  dense (GHOST=0): A_hi,A_lo,B_hi,B_lo; 3 terms; BK=32
//  ghost mlp (GHOST=1,ALO=1): A_hi,A_lo,B; 2 terms; BK=64
//  ghost head (GHOST=1,ALO=0): A_hi,B; 1 term; BK=64
template<int GHOST, int ALO, int BIAS, int GELU, int RESID, int OUTSPLIT>
__global__ void __launch_bounds__(256, 2)
hgemm(const __half* __restrict__ Ahi, const __half* __restrict__ Alo,
      const __half* __restrict__ Bhi, const __half* __restrict__ Blo,
      const float* __restrict__ bias, const float* __restrict__ scale,
      const float* __restrict__ S0, const float* __restrict__ lutp,
      const float* __restrict__ resid,
      float* __restrict__ C, __half* __restrict__ Ohi, __half* __restrict__ Olo,
      int M, int N, int K) {
    constexpr int BK     = GHOST ? 64 : 32;
    constexpr int ROWB   = GHOST ? 144 : 80;
    constexpr int PLANE  = GHOST ? 18432 : 10240;
    constexpr int APL    = 1 + ALO;                 // # A planes
    constexpr int PLANES = APL + (GHOST ? 1 : 2);
    constexpr int STAGE_B = PLANES * PLANE;
    constexpr int KS_N   = BK / 16;
    constexpr int CHSH   = GHOST ? 3 : 2;
    constexpr int REPS   = GHOST ? 4 : 2;

    extern __shared__ __align__(128) char sm[];
    uint32_t smb = smem_u32(sm);

    int tid = threadIdx.x, wid = tid >> 5, lane = tid & 31;
    int grp = lane >> 2, tg = lane & 3;
    int wm = (wid & 1) * 64;
    int wn = (wid >> 1) * 32;
    int bm = blockIdx.x * 128;
    int bn = blockIdx.y * 128;

    float acc[16][4];
    #pragma unroll
    for (int i = 0; i < 16; i++)
        #pragma unroll
        for (int e = 0; e < 4; e++) acc[i][e] = 0.f;

    int nch = K / BK;

    auto issue = [&](int c) {
        uint32_t sb = smb + (uint32_t)(c & 1) * STAGE_B;
        int kb = c * BK;
        #pragma unroll
        for (int rep = 0; rep < REPS; rep++) {
            int cid = tid + rep * 256;
            int row = cid >> CHSH, ch = cid & ((1 << CHSH) - 1);
            uint32_t doff = (uint32_t)(row * ROWB + ch * 16);
            size_t ga = (size_t)(bm + row) * K + kb + ch * 8;
            cp16(sb + doff, Ahi + ga);
            if (ALO) cp16(sb + PLANE + doff, Alo + ga);
            int br = bn + row; if (br >= N) br = N - 1;
            size_t gb = (size_t)br * K + kb + ch * 8;
            cp16(sb + APL * PLANE + doff, Bhi + gb);
            if (!GHOST) cp16(sb + (APL + 1) * PLANE + doff, Blo + gb);
        }
        CP_COMMIT();
    };

    issue(0);
    if (nch > 1) issue(1);

    uint32_t aoffL = (uint32_t)((wm + (lane & 15)) * ROWB + ((lane >> 4) << 4));
    uint32_t boffL = (uint32_t)((wn + (lane & 7) + ((lane >> 4) << 3)) * ROWB
                                + (((lane >> 3) & 1) << 4));

    for (int c = 0; c < nch; c++) {
        if (c + 1 < nch) CP_WAIT1(); else CP_WAIT0();
        __syncthreads();

        uint32_t sb = smb + (uint32_t)(c & 1) * STAGE_B;
        #pragma unroll
        for (int ks = 0; ks < KS_N; ks++) {
            uint32_t ao = sb + aoffL + ks * 32;
            uint32_t bo = sb + APL * PLANE + boffL + ks * 32;
            unsigned ah[4][4], al[4][4], bh[4][2], bl[4][2];
            #pragma unroll
            for (int i = 0; i < 4; i++) {
                LDSM4(ah[i][0], ah[i][1], ah[i][2], ah[i][3], ao + i * 16 * ROWB);
                if (ALO)
                    LDSM4(al[i][0], al[i][1], al[i][2], al[i][3], ao + PLANE + i * 16 * ROWB);
            }
            #pragma unroll
            for (int j2 = 0; j2 < 2; j2++) {
                unsigned r0, r1, r2, r3;
                LDSM4(r0, r1, r2, r3, bo + j2 * 16 * ROWB);
                bh[j2 * 2][0] = r0; bh[j2 * 2][1] = r1;
                bh[j2 * 2 + 1][0] = r2; bh[j2 * 2 + 1][1] = r3;
                if (!GHOST) {
                    LDSM4(r0, r1, r2, r3, bo + PLANE + j2 * 16 * ROWB);
                    bl[j2 * 2][0] = r0; bl[j2 * 2][1] = r1;
                    bl[j2 * 2 + 1][0] = r2; bl[j2 * 2 + 1][1] = r3;
                }
            }
            #pragma unroll
            for (int i = 0; i < 4; i++)
                #pragma unroll
                for (int j = 0; j < 4; j++) {
                    float* a4 = acc[i * 4 + j];
                    MMA16816(a4, ah[i][0], ah[i][1], ah[i][2], ah[i][3], bh[j][0], bh[j][1]);
                    if (ALO)
                        MMA16816(a4, al[i][0], al[i][1], al[i][2], al[i][3], bh[j][0], bh[j][1]);
                    if (!GHOST)
                        MMA16816(a4, ah[i][0], ah[i][1], ah[i][2], ah[i][3], bl[j][0], bl[j][1]);
                }
        }
        __syncthreads();
        if (c + 2 < nch) issue(c + 2);
    }

    // ---- epilogue ----
    float c0f = 0.f, c1f = 0.f;
    if (GHOST) {
        float L0 = __ldg(lutp), L255 = __ldg(lutp + 255);
        c0f = L0;
        c1f = (L255 - L0) * (1.0f / 255.0f);
    }
    #pragma unroll
    for (int i = 0; i < 4; i++) {
        int mA = bm + wm + i * 16 + grp;
        float s0a = 0.f, s0b = 0.f;
        if (GHOST) { s0a = S0[mA]; s0b = S0[mA + 8]; }
        #pragma unroll
        for (int j = 0; j < 4; j++) {
            int n0 = bn + wn + j * 8 + 2 * tg;
            #pragma unroll
            for (int e = 0; e < 4; e++) {
                int m = mA + ((e >= 2) ? 8 : 0);
                int n = n0 + (e & 1);
                if (n < N) {
                    float t = acc[i * 4 + j][e];
                    if (GHOST) t = (c1f * t + c0f * ((e >= 2) ? s0b : s0a)) * scale[n];
                    if (BIAS)  t += bias[n];
                    if (GELU)  t = gelu_tanh(t);
                    if (RESID) t += resid[(size_t)m * N + n];
                    if (OUTSPLIT) {
                        __half hh, ll; split1(t, hh, ll);
                        Ohi[(size_t)m * N + n] = hh;
                        Olo[(size_t)m * N + n] = ll;
                    } else {
                        C[(size_t)m * N + n] = t;
                    }
                }
            }
        }
    }
}

// ---------------- launch ----------------
extern "C" void kernel_launch(void* const* d_in, const int* in_sizes, int n_in,
                              void* d_out, int out_size) {
    const float* lut        = (const float*)d_in[0];
    const float* tok_emb    = (const float*)d_in[1];
    const float* pos_emb    = (const float*)d_in[2];
    const float* ln1_g      = (const float*)d_in[3];
    const float* ln1_b      = (const float*)d_in[4];
    const float* in_w       = (const float*)d_in[5];
    const float* in_b       = (const float*)d_in[6];
    const float* out_w      = (const float*)d_in[7];
    const float* out_b      = (const float*)d_in[8];
    const float* ln2_g      = (const float*)d_in[9];
    const float* ln2_b      = (const float*)d_in[10];
    const float* mlp1_scale = (const float*)d_in[11];
    const float* mlp2_scale = (const float*)d_in[12];
    const float* lnf_g      = (const float*)d_in[13];
    const float* lnf_b      = (const float*)d_in[14];
    const float* head_scale = (const float*)d_in[15];
    const int*   mlp1_idx   = (const int*)d_in[16];
    const int*   mlp2_idx   = (const int*)d_in[17];
    const int*   head_idx   = (const int*)d_in[18];
    const int*   idx        = (const int*)d_in[19];
    float* out = (float*)d_out;

    float *x, *qkv, *s0_ln, *s0_mlp;
    __half *ln_hi, *ln_lo, *att_hi, *att_lo, *mlp_hi, *mlp_lo;
    __half *wq_hi, *wq_lo, *wp_hi, *wp_lo, *w1_i, *w2_i, *wh_i;
    cudaGetSymbolAddress((void**)&x,      g_x);
    cudaGetSymbolAddress((void**)&qkv,    g_qkv);
    cudaGetSymbolAddress((void**)&s0_ln,  g_s0_ln);
    cudaGetSymbolAddress((void**)&s0_mlp, g_s0_mlp);
    cudaGetSymbolAddress((void**)&ln_hi,  g_ln_hi);
    cudaGetSymbolAddress((void**)&ln_lo,  g_ln_lo);
    cudaGetSymbolAddress((void**)&att_hi, g_att_hi);
    cudaGetSymbolAddress((void**)&att_lo, g_att_lo);
    cudaGetSymbolAddress((void**)&mlp_hi, g_mlp_hi);
    cudaGetSymbolAddress((void**)&mlp_lo, g_mlp_lo);
    cudaGetSymbolAddress((void**)&wq_hi,  w_qkv_hi);
    cudaGetSymbolAddress((void**)&wq_lo,  w_qkv_lo);
    cudaGetSymbolAddress((void**)&wp_hi,  w_proj_hi);
    cudaGetSymbolAddress((void**)&wp_lo,  w_proj_lo);
    cudaGetSymbolAddress((void**)&w1_i,   w_mlp1_i);
    cudaGetSymbolAddress((void**)&w2_i,   w_mlp2_i);
    cudaGetSymbolAddress((void**)&wh_i,   w_head_i);

    static int attr_done = 0;
    if (!attr_done) {
        cudaFuncSetAttribute(hgemm<0,1,1,0,0,0>, cudaFuncAttributeMaxDynamicSharedMemorySize, SM_DENSE);
        cudaFuncSetAttribute(hgemm<0,1,1,0,1,0>, cudaFuncAttributeMaxDynamicSharedMemorySize, SM_DENSE);
        cudaFuncSetAttribute(hgemm<1,1,0,1,0,1>, cudaFuncAttributeMaxDynamicSharedMemorySize, SM_GHOST);
        cudaFuncSetAttribute(hgemm<1,1,0,0,1,0>, cudaFuncAttributeMaxDynamicSharedMemorySize, SM_GHOST);
        cudaFuncSetAttribute(hgemm<1,0,0,0,0,0>, cudaFuncAttributeMaxDynamicSharedMemorySize, SM_HEAD);
        cudaFuncSetAttribute(flash_attn,         cudaFuncAttributeMaxDynamicSharedMemorySize, SM_ATTN);
        attr_done = 1;
    }

    conv_all<<<NB0 + NB1 + NB2 + NB3 + NB4, 256>>>(
        in_w, out_w, mlp1_idx, mlp2_idx, head_idx,
        wq_hi, wq_lo, wp_hi, wp_lo, w1_i, w2_i, wh_i);

    embed_kernel<<<BT, 256>>>(idx, tok_emb, pos_emb, x);

    for (int l = 0; l < NL; l++) {
        ln_kernel<<<BT, 256>>>(x, ln1_g + l * DIMN, ln1_b + l * DIMN, ln_hi, ln_lo, s0_ln);
        {
            dim3 grid(BT / 128, QKVW / 128);   // 16 x 18
            hgemm<0,1,1,0,0,0><<<grid, 256, SM_DENSE>>>(
                ln_hi, ln_lo,
                wq_hi + (size_t)l * QKVW * DIMN, wq_lo + (size_t)l * QKVW * DIMN,
                in_b + (size_t)l * QKVW, nullptr, nullptr, nullptr, nullptr,
                qkv, nullptr, nullptr, BT, QKVW, DIMN);
        }
        {
            dim3 grid(SEQ / QT, NH, BATCH);    // 8 x 12 x 4
            flash_attn<<<grid, 256, SM_ATTN>>>(qkv, att_hi, att_lo);
        }
        {
            dim3 grid(BT / 128, DIMN / 128);   // 16 x 6
            hgemm<0,1,1,0,1,0><<<grid, 256, SM_DENSE>>>(
                att_hi, att_lo,
                wp_hi + (size_t)l * DIMN * DIMN, wp_lo + (size_t)l * DIMN * DIMN,
                out_b + (size_t)l * DIMN, nullptr, nullptr, nullptr, x,
                x, nullptr, nullptr, BT, DIMN, DIMN);
        }
        ln_kernel<<<BT, 256>>>(x, ln2_g + l * DIMN, ln2_b + l * DIMN, ln_hi, ln_lo, s0_ln);
        {
            dim3 grid(BT / 128, HID / 128);    // 16 x 24
            hgemm<1,1,0,1,0,1><<<grid, 256, SM_GHOST>>>(
                ln_hi, ln_lo,
                w1_i + (size_t)l * HID * DIMN, nullptr,
                nullptr, mlp1_scale + (size_t)l * HID, s0_ln, lut, nullptr,
                nullptr, mlp_hi, mlp_lo, BT, HID, DIMN);
        }
        rowsum_kernel<<<BT, 256>>>(mlp_hi, mlp_lo, s0_mlp, HID);
        {
            dim3 grid(BT / 128, DIMN / 128);   // 16 x 6
            hgemm<1,1,0,0,1,0><<<grid, 256, SM_GHOST>>>(
                mlp_hi, mlp_lo,
                w2_i + (size_t)l * DIMN * HID, nullptr,
                nullptr, mlp2_scale + (size_t)l * DIMN, s0_mlp, lut, x,
                x, nullptr, nullptr, BT, DIMN, HID);
        }
    }

    ln_kernel<<<BT, 256>>>(x, lnf_g, lnf_b, ln_hi, ln_lo, s0_ln);

    {
        dim3 grid(BT / 128, (VOCAB + 127) / 128);   // 16 x 393
        hgemm<1,0,0,0,0,0><<<grid, 256, SM_HEAD>>>(
            ln_hi, nullptr, wh_i, nullptr,
            nullptr, head_scale, s0_ln, lut, nullptr,
            out, nullptr, nullptr, BT, VOCAB, DIMN);
    }
}

// round 15
// speedup vs baseline: 1.0321x; 1.0321x over previous
#include <cuda_runtime.h>
#include <cuda_fp16.h>
#include <cstdint>
#include <math.h>

// ---------------- problem constants ----------------
#define DIMN 768
#define NL   13
#define NH   12
#define HD   64
#define VOCAB 50257
#define SEQ  512
#define BATCH 4
#define HID  3072
#define BT   (BATCH*SEQ)      // 2048
#define QKVW (3*DIMN)         // 2304

// ---------------- gemm config ----------------
#define SM_DENSE (2 * 4 * 10240)   // 81920
#define SM_GHOST (2 * 3 * 18432)   // 110592
#define SM_HEAD  (2 * 2 * 18432)   // 73728

// ---------------- flash attention config ----------------
#define QT 64
#define KT 64
#define SM_ATTN (4 * 64 * 64 * 4)  // 65536 bytes (Q,K,V,P swizzled 64x64 tiles)

// ---------------- scratch ----------------
__device__ float  g_x   [(size_t)BT*DIMN];
__device__ float  g_qkv [(size_t)BT*QKVW];
__device__ float  g_s0_ln [BT];
__device__ float  g_s0_mlp[BT];
__device__ __half g_ln_hi [(size_t)BT*DIMN];
__device__ __half g_ln_lo [(size_t)BT*DIMN];
__device__ __half g_att_hi[(size_t)BT*DIMN];
__device__ __half g_att_lo[(size_t)BT*DIMN];
__device__ __half g_mlp_hi[(size_t)BT*HID];
__device__ __half g_mlp_lo[(size_t)BT*HID];
__device__ __half w_qkv_hi [(size_t)NL*QKVW*DIMN];
__device__ __half w_qkv_lo [(size_t)NL*QKVW*DIMN];
__device__ __half w_proj_hi[(size_t)NL*DIMN*DIMN];
__device__ __half w_proj_lo[(size_t)NL*DIMN*DIMN];
__device__ __half w_mlp1_i [(size_t)NL*HID*DIMN];
__device__ __half w_mlp2_i [(size_t)NL*DIMN*HID];
__device__ __half w_head_i [(size_t)VOCAB*DIMN];

// ---------------- helpers ----------------
__device__ __forceinline__ void split1(float v, __half& h, __half& l) {
    h = __float2half_rn(v);
    l = __float2half_rn(v - __half2float(h));
}
__device__ __forceinline__ float gelu_tanh(float x) {
    float x3 = x * x * x;
    return 0.5f * x * (1.0f + tanhf(0.7978845608028654f * (x + 0.044715f * x3)));
}
__device__ __forceinline__ uint32_t smem_u32(const void* p) {
    uint32_t a;
    asm("{ .reg .u64 t; cvta.to.shared.u64 t, %1; cvt.u32.u64 %0, t; }" : "=r"(a) : "l"(p));
    return a;
}
__device__ __forceinline__ void cp16(uint32_t dst, const void* src) {
    asm volatile("cp.async.cg.shared.global [%0], [%1], 16;" :: "r"(dst), "l"(src));
}
#define CP_COMMIT() asm volatile("cp.async.commit_group;" ::: "memory")
#define CP_WAIT1()  asm volatile("cp.async.wait_group 1;" ::: "memory")
#define CP_WAIT0()  asm volatile("cp.async.wait_group 0;" ::: "memory")

#define LDSM4(r0, r1, r2, r3, addr)                                           \
    asm volatile("ldmatrix.sync.aligned.m8n8.x4.shared.b16 {%0,%1,%2,%3}, [%4];" \
        : "=r"(r0), "=r"(r1), "=r"(r2), "=r"(r3) : "r"(addr))

#define MMA16816(c, a0, a1, a2, a3, b0, b1)                                   \
    asm volatile(                                                             \
        "mma.sync.aligned.m16n8k16.row.col.f32.f16.f16.f32 "                  \
        "{%0,%1,%2,%3}, {%4,%5,%6,%7}, {%8,%9}, {%0,%1,%2,%3};"               \
        : "+f"((c)[0]), "+f"((c)[1]), "+f"((c)[2]), "+f"((c)[3])              \
        : "r"(a0), "r"(a1), "r"(a2), "r"(a3), "r"(b0), "r"(b1))

// warp+block reduce (256 threads)
__device__ __forceinline__ float blk_sum(float v, float* sred, int tid) {
    #pragma unroll
    for (int o = 16; o > 0; o >>= 1) v += __shfl_xor_sync(0xffffffffu, v, o);
    if ((tid & 31) == 0) sred[tid >> 5] = v;
    __syncthreads();
    float t = sred[0] + sred[1] + sred[2] + sred[3]
            + sred[4] + sred[5] + sred[6] + sred[7];
    __syncthreads();
    return t;
}

// swizzled 64x64 float tile addressing (16B-chunk XOR)
__device__ __forceinline__ int swz(int r, int c) {
    return r * 64 + ((((c >> 2) ^ ((r >> 2) & 15)) << 2) | (c & 3));
}

// ---------------- merged conversion kernel ----------------
#define N0 ((size_t)NL*QKVW*DIMN)
#define N1 ((size_t)NL*DIMN*DIMN)
#define N2 ((size_t)NL*HID*DIMN)
#define N3 ((size_t)NL*DIMN*HID)
#define N4 ((size_t)VOCAB*DIMN)
#define NB0 ((unsigned)(N0/1024))
#define NB1 ((unsigned)(N1/1024))
#define NB2 ((unsigned)(N2/2048))
#define NB3 ((unsigned)(N3/2048))
#define NB4 ((unsigned)((N4+2047)/2048))

__device__ __forceinline__ void conv_w_body(const float* __restrict__ w,
                                            __half* __restrict__ hi, __half* __restrict__ lo,
                                            size_t n, unsigned blk) {
    size_t i = ((size_t)blk * 256 + threadIdx.x) * 4;
    if (i >= n) return;
    float4 v = *(const float4*)(w + i);
    __half h[4], l[4];
    split1(v.x, h[0], l[0]); split1(v.y, h[1], l[1]);
    split1(v.z, h[2], l[2]); split1(v.w, h[3], l[3]);
    *(ushort4*)(hi + i) = make_ushort4(__half_as_ushort(h[0]), __half_as_ushort(h[1]),
                                       __half_as_ushort(h[2]), __half_as_ushort(h[3]));
    *(ushort4*)(lo + i) = make_ushort4(__half_as_ushort(l[0]), __half_as_ushort(l[1]),
                                       __half_as_ushort(l[2]), __half_as_ushort(l[3]));
}
__device__ __forceinline__ void conv_i_body(const int* __restrict__ idx,
                                            __half* __restrict__ o, size_t n, unsigned blk) {
    size_t i = ((size_t)blk * 256 + threadIdx.x) * 8;
    if (i >= n) return;
    int4 a = *(const int4*)(idx + i);
    int4 b = *(const int4*)(idx + i + 4);
    int id[8] = {a.x, a.y, a.z, a.w, b.x, b.y, b.z, b.w};
    ushort h[8];
    #pragma unroll
    for (int j = 0; j < 8; j++)
        h[j] = __half_as_ushort(__float2half_rn((float)id[j]));
    *(uint4*)(o + i) = *(uint4*)h;
}

__global__ void conv_all(const float* __restrict__ in_w,  const float* __restrict__ out_w,
                         const int* __restrict__ i1, const int* __restrict__ i2,
                         const int* __restrict__ ih,
                         __half* __restrict__ wq_hi_, __half* __restrict__ wq_lo_,
                         __half* __restrict__ wp_hi_, __half* __restrict__ wp_lo_,
                         __half* __restrict__ w1_, __half* __restrict__ w2_,
                         __half* __restrict__ wh_) {
    unsigned b = blockIdx.x;
    if (b < NB0) { conv_w_body(in_w,  wq_hi_, wq_lo_, N0, b); return; }
    b -= NB0;
    if (b < NB1) { conv_w_body(out_w, wp_hi_, wp_lo_, N1, b); return; }
    b -= NB1;
    if (b < NB2) { conv_i_body(i1, w1_, N2, b); return; }
    b -= NB2;
    if (b < NB3) { conv_i_body(i2, w2_, N3, b); return; }
    b -= NB3;
    conv_i_body(ih, wh_, N4, b);
}

// ---------------- embedding ----------------
__global__ void embed_kernel(const int* __restrict__ idx, const float* __restrict__ tok,
                             const float* __restrict__ pos, float* __restrict__ x) {
    int r = blockIdx.x;
    int t = r % SEQ;
    int token = idx[r];
    const float* tr = tok + (size_t)token * DIMN;
    const float* pr = pos + (size_t)t * DIMN;
    float* xr = x + (size_t)r * DIMN;
    for (int d = threadIdx.x; d < DIMN; d += blockDim.x)
        xr[d] = tr[d] + pr[d];
}

// ---------------- layernorm -> split planes + rowsum ----------------
__global__ void ln_kernel(const float* __restrict__ x, const float* __restrict__ g,
                          const float* __restrict__ b,
                          __half* __restrict__ ohi, __half* __restrict__ olo,
                          float* __restrict__ s0) {
    int r = blockIdx.x;
    int tid = threadIdx.x;
    const float* xr = x + (size_t)r * DIMN;
    __shared__ float sred[8];

    float v0 = xr[tid], v1 = xr[tid + 256], v2 = xr[tid + 512];
    float mean = blk_sum(v0 + v1 + v2, sred, tid) * (1.0f / DIMN);
    float d0 = v0 - mean, d1 = v1 - mean, d2 = v2 - mean;
    float var = blk_sum(d0 * d0 + d1 * d1 + d2 * d2, sred, tid) * (1.0f / DIMN);
    float inv = rsqrtf(var + 1e-5f);
    float o0 = d0 * inv * g[tid]       + b[tid];
    float o1 = d1 * inv * g[tid + 256] + b[tid + 256];
    float o2 = d2 * inv * g[tid + 512] + b[tid + 512];
    float tot = blk_sum(o0 + o1 + o2, sred, tid);
    if (tid == 0) s0[r] = tot;
    __half h, l;
    size_t base = (size_t)r * DIMN;
    split1(o0, h, l); ohi[base + tid]       = h; olo[base + tid]       = l;
    split1(o1, h, l); ohi[base + tid + 256] = h; olo[base + tid + 256] = l;
    split1(o2, h, l); ohi[base + tid + 512] = h; olo[base + tid + 512] = l;
}

// ---------------- rowsum of split planes ----------------
__global__ void rowsum_kernel(const __half* __restrict__ hi, const __half* __restrict__ lo,
                              float* __restrict__ s0, int K) {
    int r = blockIdx.x;
    int tid = threadIdx.x;
    __shared__ float sred[8];
    float s = 0.f;
    for (int k = tid * 4; k < K; k += 1024) {
        float2 h2 = __half22float2(*(const __half2*)(hi + (size_t)r * K + k));
        float2 h3 = __half22float2(*(const __half2*)(hi + (size_t)r * K + k + 2));
        float2 l2 = __half22float2(*(const __half2*)(lo + (size_t)r * K + k));
        float2 l3 = __half22float2(*(const __half2*)(lo + (size_t)r * K + k + 2));
        s += h2.x + h2.y + h3.x + h3.y + l2.x + l2.y + l3.x + l3.y;
    }
    float tot = blk_sum(s, sred, tid);
    if (tid == 0) s0[r] = tot;
}

// ---------------- flash attention (float4 + swizzle) ----------------
__global__ void __launch_bounds__(256)
flash_attn(const float* __restrict__ qkv,
           __half* __restrict__ ohi, __half* __restrict__ olo) {
    extern __shared__ float smf[];
    float* Qs = smf;                  // swizzled [64][64]
    float* Ks = Qs + 64 * 64;
    float* Vs = Ks + 64 * 64;
    float* Ps = Vs + 64 * 64;

    int qt = blockIdx.x, h = blockIdx.y, b = blockIdx.z;
    int tid = threadIdx.x;
    int ty = tid >> 4, tx = tid & 15;
    int q0 = qt * QT;

    // load Q tile (scale folded)
    for (int i = tid; i < QT * 16; i += 256) {
        int r = i >> 4, c4 = (i & 15) * 4;
        const float* src = qkv + ((size_t)(b * SEQ + q0 + r)) * QKVW + h * HD + c4;
        float4 v = *(const float4*)src;
        v.x *= 0.125f; v.y *= 0.125f; v.z *= 0.125f; v.w *= 0.125f;
        *(float4*)&Qs[swz(r, c4)] = v;
    }

    float m[4], l[4], O[4][4];
    #pragma unroll
    for (int i = 0; i < 4; i++) {
        m[i] = -1e30f; l[i] = 0.f;
        #pragma unroll
        for (int j = 0; j < 4; j++) O[i][j] = 0.f;
    }
    __syncthreads();

    for (int kt = 0; kt <= qt; kt++) {
        int k0 = kt * KT;
        for (int i = tid; i < KT * 16; i += 256) {
            int r = i >> 4, c4 = (i & 15) * 4;
            size_t rowb = ((size_t)(b * SEQ + k0 + r)) * QKVW + h * HD + c4;
            *(float4*)&Ks[swz(r, c4)] = *(const float4*)(qkv + rowb + DIMN);
            *(float4*)&Vs[swz(r, c4)] = *(const float4*)(qkv + rowb + 2 * DIMN);
        }
        __syncthreads();

        // S = Q K^T  (float4 over d)
        float s[4][4];
        #pragma unroll
        for (int i = 0; i < 4; i++)
            #pragma unroll
            for (int j = 0; j < 4; j++) s[i][j] = 0.f;
        #pragma unroll 4
        for (int d4 = 0; d4 < HD; d4 += 4) {
            float4 qv[4], kv[4];
            #pragma unroll
            for (int i = 0; i < 4; i++) qv[i] = *(const float4*)&Qs[swz(ty * 4 + i, d4)];
            #pragma unroll
            for (int j = 0; j < 4; j++) kv[j] = *(const float4*)&Ks[swz(tx * 4 + j, d4)];
            #pragma unroll
            for (int i = 0; i < 4; i++)
                #pragma unroll
                for (int j = 0; j < 4; j++) {
                    s[i][j] = fmaf(qv[i].x, kv[j].x, s[i][j]);
                    s[i][j] = fmaf(qv[i].y, kv[j].y, s[i][j]);
                    s[i][j] = fmaf(qv[i].z, kv[j].z, s[i][j]);
                    s[i][j] = fmaf(qv[i].w, kv[j].w, s[i][j]);
                }
        }
        if (kt == qt) {
            #pragma unroll
            for (int i = 0; i < 4; i++)
                #pragma unroll
                for (int j = 0; j < 4; j++)
                    if (k0 + tx * 4 + j > q0 + ty * 4 + i) s[i][j] = -1e30f;
        }

        // row max (across tx lanes; bit4=ty untouched)
        float mt[4];
        #pragma unroll
        for (int i = 0; i < 4; i++)
            mt[i] = fmaxf(fmaxf(s[i][0], s[i][1]), fmaxf(s[i][2], s[i][3]));
        #pragma unroll
        for (int o = 1; o < 16; o <<= 1)
            #pragma unroll
            for (int i = 0; i < 4; i++)
                mt[i] = fmaxf(mt[i], __shfl_xor_sync(0xffffffffu, mt[i], o));

        float ps[4];
        #pragma unroll
        for (int i = 0; i < 4; i++) {
            float mn = fmaxf(m[i], mt[i]);
            float sc = __expf(m[i] - mn);
            m[i] = mn;
            l[i] *= sc;
            float4 p4;
            p4.x = __expf(s[i][0] - mn);
            p4.y = __expf(s[i][1] - mn);
            p4.z = __expf(s[i][2] - mn);
            p4.w = __expf(s[i][3] - mn);
            *(float4*)&Ps[swz(ty * 4 + i, tx * 4)] = p4;
            ps[i] = p4.x + p4.y + p4.z + p4.w;
            #pragma unroll
            for (int j = 0; j < 4; j++) O[i][j] *= sc;
        }
        #pragma unroll
        for (int o = 1; o < 16; o <<= 1)
            #pragma unroll
            for (int i = 0; i < 4; i++)
                ps[i] += __shfl_xor_sync(0xffffffffu, ps[i], o);
        #pragma unroll
        for (int i = 0; i < 4; i++) l[i] += ps[i];
        __syncthreads();

        // O += P V (float4 over k)
        #pragma unroll 4
        for (int k4 = 0; k4 < KT; k4 += 4) {
            float4 pv[4], vv[4];
            #pragma unroll
            for (int i = 0; i < 4; i++) pv[i] = *(const float4*)&Ps[swz(ty * 4 + i, k4)];
            #pragma unroll
            for (int kk = 0; kk < 4; kk++) vv[kk] = *(const float4*)&Vs[swz(k4 + kk, tx * 4)];
            #pragma unroll
            for (int i = 0; i < 4; i++) {
                O[i][0] = fmaf(pv[i].x, vv[0].x, O[i][0]);
                O[i][1] = fmaf(pv[i].x, vv[0].y, O[i][1]);
                O[i][2] = fmaf(pv[i].x, vv[0].z, O[i][2]);
                O[i][3] = fmaf(pv[i].x, vv[0].w, O[i][3]);
                O[i][0] = fmaf(pv[i].y, vv[1].x, O[i][0]);
                O[i][1] = fmaf(pv[i].y, vv[1].y, O[i][1]);
                O[i][2] = fmaf(pv[i].y, vv[1].z, O[i][2]);
                O[i][3] = fmaf(pv[i].y, vv[1].w, O[i][3]);
                O[i][0] = fmaf(pv[i].z, vv[2].x, O[i][0]);
                O[i][1] = fmaf(pv[i].z, vv[2].y, O[i][1]);
                O[i][2] = fmaf(pv[i].z, vv[2].z, O[i][2]);
                O[i][3] = fmaf(pv[i].z, vv[2].w, O[i][3]);
                O[i][0] = fmaf(pv[i].w, vv[3].x, O[i][0]);
                O[i][1] = fmaf(pv[i].w, vv[3].y, O[i][1]);
                O[i][2] = fmaf(pv[i].w, vv[3].z, O[i][2]);
                O[i][3] = fmaf(pv[i].w, vv[3].w, O[i][3]);
            }
        }
        __syncthreads();
    }

    #pragma unroll
    for (int i = 0; i < 4; i++) {
        float inv = 1.0f / l[i];
        size_t base = ((size_t)(b * SEQ + q0 + ty * 4 + i)) * DIMN + h * HD + tx * 4;
        #pragma unroll
        for (int j = 0; j < 4; j++) {
            float val = O[i][j] * inv;
            __half hh, ll; split1(val, hh, ll);
            ohi[base + j] = hh; olo[base + j] = ll;
        }
    }
}

// ---------------- HMMA GEMM ----------------
// dense (GHOST=0): 3 terms; BK=32 | ghost mlp (1,ALO=1): 2 terms; BK=64 | head (1,0): 1 term
template<int GHOST, int ALO, int BIAS, int GELU, int RESID, int OUTSPLIT>
__global__ void __launch_bounds__(256, 2)
hgemm(const __half* __restrict__ Ahi, const __half* __restrict__ Alo,
      const __half* __restrict__ Bhi, const __half* __restrict__ Blo,
      const float* __restrict__ bias, const float* __restrict__ scale,
      const float* __restrict__ S0, const float* __restrict__ lutp,
      const float* __restrict__ resid,
      float* __restrict__ C, __half* __restrict__ Ohi, __half* __restrict__ Olo,
      int M, int N, int K) {
    constexpr int BK     = GHOST ? 64 : 32;
    constexpr int ROWB   = GHOST ? 144 : 80;
    constexpr int PLANE  = GHOST ? 18432 : 10240;
    constexpr int APL    = 1 + ALO;
    constexpr int PLANES = APL + (GHOST ? 1 : 2);
    constexpr int STAGE_B = PLANES * PLANE;
    constexpr int KS_N   = BK / 16;
    constexpr int CHSH   = GHOST ? 3 : 2;
    constexpr int REPS   = GHOST ? 4 : 2;

    extern __shared__ __align__(128) char sm[];
    uint32_t smb = smem_u32(sm);

    int tid = threadIdx.x, wid = tid >> 5, lane = tid & 31;
    int grp = lane >> 2, tg = lane & 3;
    int wm = (wid & 1) * 64;
    int wn = (wid >> 1) * 32;
    int bm = blockIdx.x * 128;
    int bn = blockIdx.y * 128;

    float acc[16][4];
    #pragma unroll
    for (int i = 0; i < 16; i++)
        #pragma unroll
        for (int e = 0; e < 4; e++) acc[i][e] = 0.f;

    int nch = K / BK;

    auto issue = [&](int c) {
        uint32_t sb = smb + (uint32_t)(c & 1) * STAGE_B;
        int kb = c * BK;
        #pragma unroll
        for (int rep = 0; rep < REPS; rep++) {
            int cid = tid + rep * 256;
            int row = cid >> CHSH, ch = cid & ((1 << CHSH) - 1);
            uint32_t doff = (uint32_t)(row * ROWB + ch * 16);
            size_t ga = (size_t)(bm + row) * K + kb + ch * 8;
            cp16(sb + doff, Ahi + ga);
            if (ALO) cp16(sb + PLANE + doff, Alo + ga);
            int br = bn + row; if (br >= N) br = N - 1;
            size_t gb = (size_t)br * K + kb + ch * 8;
            cp16(sb + APL * PLANE + doff, Bhi + gb);
            if (!GHOST) cp16(sb + (APL + 1) * PLANE + doff, Blo + gb);
        }
        CP_COMMIT();
    };

    issue(0);
    if (nch > 1) issue(1);

    uint32_t aoffL = (uint32_t)((wm + (lane & 15)) * ROWB + ((lane >> 4) << 4));
    uint32_t boffL = (uint32_t)((wn + (lane & 7) + ((lane >> 4) << 3)) * ROWB
                                + (((lane >> 3) & 1) << 4));

    for (int c = 0; c < nch; c++) {
        if (c + 1 < nch) CP_WAIT1(); else CP_WAIT0();
        __syncthreads();

        uint32_t sb = smb + (uint32_t)(c & 1) * STAGE_B;
        #pragma unroll
        for (int ks = 0; ks < KS_N; ks++) {
            uint32_t ao = sb + aoffL + ks * 32;
            uint32_t bo = sb + APL * PLANE + boffL + ks * 32;
            unsigned ah[4][4], al[4][4], bh[4][2], bl[4][2];
            #pragma unroll
            for (int i = 0; i < 4; i++) {
                LDSM4(ah[i][0], ah[i][1], ah[i][2], ah[i][3], ao + i * 16 * ROWB);
                if (ALO)
                    LDSM4(al[i][0], al[i][1], al[i][2], al[i][3], ao + PLANE + i * 16 * ROWB);
            }
            #pragma unroll
            for (int j2 = 0; j2 < 2; j2++) {
                unsigned r0, r1, r2, r3;
                LDSM4(r0, r1, r2, r3, bo + j2 * 16 * ROWB);
                bh[j2 * 2][0] = r0; bh[j2 * 2][1] = r1;
                bh[j2 * 2 + 1][0] = r2; bh[j2 * 2 + 1][1] = r3;
                if (!GHOST) {
                    LDSM4(r0, r1, r2, r3, bo + PLANE + j2 * 16 * ROWB);
                    bl[j2 * 2][0] = r0; bl[j2 * 2][1] = r1;
                    bl[j2 * 2 + 1][0] = r2; bl[j2 * 2 + 1][1] = r3;
                }
            }
            #pragma unroll
            for (int i = 0; i < 4; i++)
                #pragma unroll
                for (int j = 0; j < 4; j++) {
                    float* a4 = acc[i * 4 + j];
                    MMA16816(a4, ah[i][0], ah[i][1], ah[i][2], ah[i][3], bh[j][0], bh[j][1]);
                    if (ALO)
                        MMA16816(a4, al[i][0], al[i][1], al[i][2], al[i][3], bh[j][0], bh[j][1]);
                    if (!GHOST)
                        MMA16816(a4, ah[i][0], ah[i][1], ah[i][2], ah[i][3], bl[j][0], bl[j][1]);
                }
        }
        __syncthreads();
        if (c + 2 < nch) issue(c + 2);
    }

    // ---- epilogue ----
    float c0f = 0.f, c1f = 0.f;
    if (GHOST) {
        float L0 = __ldg(lutp), L255 = __ldg(lutp + 255);
        c0f = L0;
        c1f = (L255 - L0) * (1.0f / 255.0f);
    }
    #pragma unroll
    for (int i = 0; i < 4; i++) {
        int mA = bm + wm + i * 16 + grp;
        float s0a = 0.f, s0b = 0.f;
        if (GHOST) { s0a = S0[mA]; s0b = S0[mA + 8]; }
        #pragma unroll
        for (int j = 0; j < 4; j++) {
            int n0 = bn + wn + j * 8 + 2 * tg;
            #pragma unroll
            for (int e = 0; e < 4; e++) {
                int m = mA + ((e >= 2) ? 8 : 0);
                int n = n0 + (e & 1);
                if (n < N) {
                    float t = acc[i * 4 + j][e];
                    if (GHOST) t = (c1f * t + c0f * ((e >= 2) ? s0b : s0a)) * scale[n];
                    if (BIAS)  t += bias[n];
                    if (GELU)  t = gelu_tanh(t);
                    if (RESID) t += resid[(size_t)m * N + n];
                    if (OUTSPLIT) {
                        __half hh, ll; split1(t, hh, ll);
                        Ohi[(size_t)m * N + n] = hh;
                        Olo[(size_t)m * N + n] = ll;
                    } else {
                        C[(size_t)m * N + n] = t;
                    }
                }
            }
        }
    }
}

// ---------------- launch ----------------
extern "C" void kernel_launch(void* const* d_in, const int* in_sizes, int n_in,
                              void* d_out, int out_size) {
    const float* lut        = (const float*)d_in[0];
    const float* tok_emb    = (const float*)d_in[1];
    const float* pos_emb    = (const float*)d_in[2];
    const float* ln1_g      = (const float*)d_in[3];
    const float* ln1_b      = (const float*)d_in[4];
    const float* in_w       = (const float*)d_in[5];
    const float* in_b       = (const float*)d_in[6];
    const float* out_w      = (const float*)d_in[7];
    const float* out_b      = (const float*)d_in[8];
    const float* ln2_g      = (const float*)d_in[9];
    const float* ln2_b      = (const float*)d_in[10];
    const float* mlp1_scale = (const float*)d_in[11];
    const float* mlp2_scale = (const float*)d_in[12];
    const float* lnf_g      = (const float*)d_in[13];
    const float* lnf_b      = (const float*)d_in[14];
    const float* head_scale = (const float*)d_in[15];
    const int*   mlp1_idx   = (const int*)d_in[16];
    const int*   mlp2_idx   = (const int*)d_in[17];
    const int*   head_idx   = (const int*)d_in[18];
    const int*   idx        = (const int*)d_in[19];
    float* out = (float*)d_out;

    float *x, *qkv, *s0_ln, *s0_mlp;
    __half *ln_hi, *ln_lo, *att_hi, *att_lo, *mlp_hi, *mlp_lo;
    __half *wq_hi, *wq_lo, *wp_hi, *wp_lo, *w1_i, *w2_i, *wh_i;
    cudaGetSymbolAddress((void**)&x,      g_x);
    cudaGetSymbolAddress((void**)&qkv,    g_qkv);
    cudaGetSymbolAddress((void**)&s0_ln,  g_s0_ln);
    cudaGetSymbolAddress((void**)&s0_mlp, g_s0_mlp);
    cudaGetSymbolAddress((void**)&ln_hi,  g_ln_hi);
    cudaGetSymbolAddress((void**)&ln_lo,  g_ln_lo);
    cudaGetSymbolAddress((void**)&att_hi, g_att_hi);
    cudaGetSymbolAddress((void**)&att_lo, g_att_lo);
    cudaGetSymbolAddress((void**)&mlp_hi, g_mlp_hi);
    cudaGetSymbolAddress((void**)&mlp_lo, g_mlp_lo);
    cudaGetSymbolAddress((void**)&wq_hi,  w_qkv_hi);
    cudaGetSymbolAddress((void**)&wq_lo,  w_qkv_lo);
    cudaGetSymbolAddress((void**)&wp_hi,  w_proj_hi);
    cudaGetSymbolAddress((void**)&wp_lo,  w_proj_lo);
    cudaGetSymbolAddress((void**)&w1_i,   w_mlp1_i);
    cudaGetSymbolAddress((void**)&w2_i,   w_mlp2_i);
    cudaGetSymbolAddress((void**)&wh_i,   w_head_i);

    static int attr_done = 0;
    if (!attr_done) {
        cudaFuncSetAttribute(hgemm<0,1,1,0,0,0>, cudaFuncAttributeMaxDynamicSharedMemorySize, SM_DENSE);
        cudaFuncSetAttribute(hgemm<0,1,1,0,1,0>, cudaFuncAttributeMaxDynamicSharedMemorySize, SM_DENSE);
        cudaFuncSetAttribute(hgemm<1,1,0,1,0,1>, cudaFuncAttributeMaxDynamicSharedMemorySize, SM_GHOST);
        cudaFuncSetAttribute(hgemm<1,1,0,0,1,0>, cudaFuncAttributeMaxDynamicSharedMemorySize, SM_GHOST);
        cudaFuncSetAttribute(hgemm<1,0,0,0,0,0>, cudaFuncAttributeMaxDynamicSharedMemorySize, SM_HEAD);
        cudaFuncSetAttribute(flash_attn,         cudaFuncAttributeMaxDynamicSharedMemorySize, SM_ATTN);
        attr_done = 1;
    }

    conv_all<<<NB0 + NB1 + NB2 + NB3 + NB4, 256>>>(
        in_w, out_w, mlp1_idx, mlp2_idx, head_idx,
        wq_hi, wq_lo, wp_hi, wp_lo, w1_i, w2_i, wh_i);

    embed_kernel<<<BT, 256>>>(idx, tok_emb, pos_emb, x);

    for (int l = 0; l < NL; l++) {
        ln_kernel<<<BT, 256>>>(x, ln1_g + l * DIMN, ln1_b + l * DIMN, ln_hi, ln_lo, s0_ln);
        {
            dim3 grid(BT / 128, QKVW / 128);   // 16 x 18
            hgemm<0,1,1,0,0,0><<<grid, 256, SM_DENSE>>>(
                ln_hi, ln_lo,
                wq_hi + (size_t)l * QKVW * DIMN, wq_lo + (size_t)l * QKVW * DIMN,
                in_b + (size_t)l * QKVW, nullptr, nullptr, nullptr, nullptr,
                qkv, nullptr, nullptr, BT, QKVW, DIMN);
        }
        {
            dim3 grid(SEQ / QT, NH, BATCH);    // 8 x 12 x 4
            flash_attn<<<grid, 256, SM_ATTN>>>(qkv, att_hi, att_lo);
        }
        {
            dim3 grid(BT / 128, DIMN / 128);   // 16 x 6
            hgemm<0,1,1,0,1,0><<<grid, 256, SM_DENSE>>>(
                att_hi, att_lo,
                wp_hi + (size_t)l * DIMN * DIMN, wp_lo + (size_t)l * DIMN * DIMN,
                out_b + (size_t)l * DIMN, nullptr, nullptr, nullptr, x,
                x, nullptr, nullptr, BT, DIMN, DIMN);
        }
        ln_kernel<<<BT, 256>>>(x, ln2_g + l * DIMN, ln2_b + l * DIMN, ln_hi, ln_lo, s0_ln);
        {
            dim3 grid(BT / 128, HID / 128);    // 16 x 24
            hgemm<1,1,0,1,0,1><<<grid, 256, SM_GHOST>>>(
                ln_hi, ln_lo,
                w1_i + (size_t)l * HID * DIMN, nullptr,
                nullptr, mlp1_scale + (size_t)l * HID, s0_ln, lut, nullptr,
                nullptr, mlp_hi, mlp_lo, BT, HID, DIMN);
        }
        rowsum_kernel<<<BT, 256>>>(mlp_hi, mlp_lo, s0_mlp, HID);
        {
            dim3 grid(BT / 128, DIMN / 128);   // 16 x 6
            hgemm<1,1,0,0,1,0><<<grid, 256, SM_GHOST>>>(
                mlp_hi, mlp_lo,
                w2_i + (size_t)l * DIMN * HID, nullptr,
                nullptr, mlp2_scale + (size_t)l * DIMN, s0_mlp, lut, x,
                x, nullptr, nullptr, BT, DIMN, HID);
        }
    }

    ln_kernel<<<BT, 256>>>(x, lnf_g, lnf_b, ln_hi, ln_lo, s0_ln);

    {
        dim3 grid(BT / 128, (VOCAB + 127) / 128);   // 16 x 393
        hgemm<1,0,0,0,0,0><<<grid, 256, SM_HEAD>>>(
            ln_hi, nullptr, wh_i, nullptr,
            nullptr, head_scale, s0_ln, lut, nullptr,
            out, nullptr, nullptr, BT, VOCAB, DIMN);
    }
}

// round 16
// speedup vs baseline: 1.0713x; 1.0380x over previous
#include <cuda_runtime.h>
#include <cuda_fp16.h>
#include <cstdint>
#include <math.h>

// ---------------- problem constants ----------------
#define DIMN 768
#define NL   13
#define NH   12
#define HD   64
#define VOCAB 50257
#define SEQ  512
#define BATCH 4
#define HID  3072
#define BT   (BATCH*SEQ)      // 2048
#define QKVW (3*DIMN)         // 2304

// ---------------- gemm config ----------------
#define SM_DENSE (2 * 4 * 10240)   // 81920
#define SM_GHOST (2 * 3 * 18432)   // 110592
#define SM_HEAD  (2 * 2 * 18432)   // 73728

// ---------------- flash attention config ----------------
#define QT 64
#define KT 64
#define SM_ATTN (4 * 64 * 64 * 4)  // 65536

// ---------------- scratch ----------------
__device__ float  g_x   [(size_t)BT*DIMN];
__device__ float  g_qkv [(size_t)BT*QKVW];
__device__ float  g_part[(size_t)4*BT*DIMN];   // split-K partials
__device__ float  g_s0_ln [BT];
__device__ float  g_s0_mlp[BT];
__device__ __half g_ln_hi [(size_t)BT*DIMN];
__device__ __half g_ln_lo [(size_t)BT*DIMN];
__device__ __half g_att_hi[(size_t)BT*DIMN];
__device__ __half g_att_lo[(size_t)BT*DIMN];
__device__ __half g_mlp_hi[(size_t)BT*HID];
__device__ __half g_mlp_lo[(size_t)BT*HID];
__device__ __half w_qkv_hi [(size_t)NL*QKVW*DIMN];
__device__ __half w_qkv_lo [(size_t)NL*QKVW*DIMN];
__device__ __half w_proj_hi[(size_t)NL*DIMN*DIMN];
__device__ __half w_proj_lo[(size_t)NL*DIMN*DIMN];
__device__ __half w_mlp1_i [(size_t)NL*HID*DIMN];
__device__ __half w_mlp2_i [(size_t)NL*DIMN*HID];
__device__ __half w_head_i [(size_t)VOCAB*DIMN];

// ---------------- helpers ----------------
__device__ __forceinline__ void split1(float v, __half& h, __half& l) {
    h = __float2half_rn(v);
    l = __float2half_rn(v - __half2float(h));
}
__device__ __forceinline__ float gelu_tanh(float x) {
    float x3 = x * x * x;
    return 0.5f * x * (1.0f + tanhf(0.7978845608028654f * (x + 0.044715f * x3)));
}
__device__ __forceinline__ uint32_t smem_u32(const void* p) {
    uint32_t a;
    asm("{ .reg .u64 t; cvta.to.shared.u64 t, %1; cvt.u32.u64 %0, t; }" : "=r"(a) : "l"(p));
    return a;
}
__device__ __forceinline__ void cp16(uint32_t dst, const void* src) {
    asm volatile("cp.async.cg.shared.global [%0], [%1], 16;" :: "r"(dst), "l"(src));
}
#define CP_COMMIT() asm volatile("cp.async.commit_group;" ::: "memory")
#define CP_WAIT1()  asm volatile("cp.async.wait_group 1;" ::: "memory")
#define CP_WAIT0()  asm volatile("cp.async.wait_group 0;" ::: "memory")

#define LDSM4(r0, r1, r2, r3, addr)                                           \
    asm volatile("ldmatrix.sync.aligned.m8n8.x4.shared.b16 {%0,%1,%2,%3}, [%4];" \
        : "=r"(r0), "=r"(r1), "=r"(r2), "=r"(r3) : "r"(addr))

#define MMA16816(c, a0, a1, a2, a3, b0, b1)                                   \
    asm volatile(                                                             \
        "mma.sync.aligned.m16n8k16.row.col.f32.f16.f16.f32 "                  \
        "{%0,%1,%2,%3}, {%4,%5,%6,%7}, {%8,%9}, {%0,%1,%2,%3};"               \
        : "+f"((c)[0]), "+f"((c)[1]), "+f"((c)[2]), "+f"((c)[3])              \
        : "r"(a0), "r"(a1), "r"(a2), "r"(a3), "r"(b0), "r"(b1))

// warp+block reduce (256 threads)
__device__ __forceinline__ float blk_sum(float v, float* sred, int tid) {
    #pragma unroll
    for (int o = 16; o > 0; o >>= 1) v += __shfl_xor_sync(0xffffffffu, v, o);
    if ((tid & 31) == 0) sred[tid >> 5] = v;
    __syncthreads();
    float t = sred[0] + sred[1] + sred[2] + sred[3]
            + sred[4] + sred[5] + sred[6] + sred[7];
    __syncthreads();
    return t;
}

// swizzled 64x64 float tile addressing (16B-chunk XOR)
__device__ __forceinline__ int swz(int r, int c) {
    return r * 64 + ((((c >> 2) ^ ((r >> 2) & 15)) << 2) | (c & 3));
}

// ---------------- merged conversion ----------------
#define N0 ((size_t)NL*QKVW*DIMN)
#define N1 ((size_t)NL*DIMN*DIMN)
#define N2 ((size_t)NL*HID*DIMN)
#define N3 ((size_t)NL*DIMN*HID)
#define N4 ((size_t)VOCAB*DIMN)
#define NB0 ((unsigned)(N0/1024))
#define NB1 ((unsigned)(N1/1024))
#define NB2 ((unsigned)(N2/2048))
#define NB3 ((unsigned)(N3/2048))
#define NB4 ((unsigned)((N4+2047)/2048))

__device__ __forceinline__ void conv_w_body(const float* __restrict__ w,
                                            __half* __restrict__ hi, __half* __restrict__ lo,
                                            size_t n, unsigned blk) {
    size_t i = ((size_t)blk * 256 + threadIdx.x) * 4;
    if (i >= n) return;
    float4 v = *(const float4*)(w + i);
    __half h[4], l[4];
    split1(v.x, h[0], l[0]); split1(v.y, h[1], l[1]);
    split1(v.z, h[2], l[2]); split1(v.w, h[3], l[3]);
    *(ushort4*)(hi + i) = make_ushort4(__half_as_ushort(h[0]), __half_as_ushort(h[1]),
                                       __half_as_ushort(h[2]), __half_as_ushort(h[3]));
    *(ushort4*)(lo + i) = make_ushort4(__half_as_ushort(l[0]), __half_as_ushort(l[1]),
                                       __half_as_ushort(l[2]), __half_as_ushort(l[3]));
}
__device__ __forceinline__ void conv_i_body(const int* __restrict__ idx,
                                            __half* __restrict__ o, size_t n, unsigned blk) {
    size_t i = ((size_t)blk * 256 + threadIdx.x) * 8;
    if (i >= n) return;
    int4 a = *(const int4*)(idx + i);
    int4 b = *(const int4*)(idx + i + 4);
    int id[8] = {a.x, a.y, a.z, a.w, b.x, b.y, b.z, b.w};
    ushort h[8];
    #pragma unroll
    for (int j = 0; j < 8; j++)
        h[j] = __half_as_ushort(__float2half_rn((float)id[j]));
    *(uint4*)(o + i) = *(uint4*)h;
}

__global__ void conv_all(const float* __restrict__ in_w,  const float* __restrict__ out_w,
                         const int* __restrict__ i1, const int* __restrict__ i2,
                         const int* __restrict__ ih,
                         __half* __restrict__ wq_hi_, __half* __restrict__ wq_lo_,
                         __half* __restrict__ wp_hi_, __half* __restrict__ wp_lo_,
                         __half* __restrict__ w1_, __half* __restrict__ w2_,
                         __half* __restrict__ wh_) {
    unsigned b = blockIdx.x;
    if (b < NB0) { conv_w_body(in_w,  wq_hi_, wq_lo_, N0, b); return; }
    b -= NB0;
    if (b < NB1) { conv_w_body(out_w, wp_hi_, wp_lo_, N1, b); return; }
    b -= NB1;
    if (b < NB2) { conv_i_body(i1, w1_, N2, b); return; }
    b -= NB2;
    if (b < NB3) { conv_i_body(i2, w2_, N3, b); return; }
    b -= NB3;
    conv_i_body(ih, wh_, N4, b);
}

// ---------------- embedding ----------------
__global__ void embed_kernel(const int* __restrict__ idx, const float* __restrict__ tok,
                             const float* __restrict__ pos, float* __restrict__ x) {
    int r = blockIdx.x;
    int t = r % SEQ;
    int token = idx[r];
    const float* tr = tok + (size_t)token * DIMN;
    const float* pr = pos + (size_t)t * DIMN;
    float* xr = x + (size_t)r * DIMN;
    for (int d = threadIdx.x; d < DIMN; d += blockDim.x)
        xr[d] = tr[d] + pr[d];
}

// ---------------- layernorm -> split planes + rowsum ----------------
__global__ void ln_kernel(const float* __restrict__ x, const float* __restrict__ g,
                          const float* __restrict__ b,
                          __half* __restrict__ ohi, __half* __restrict__ olo,
                          float* __restrict__ s0) {
    int r = blockIdx.x;
    int tid = threadIdx.x;
    const float* xr = x + (size_t)r * DIMN;
    __shared__ float sred[8];

    float v0 = xr[tid], v1 = xr[tid + 256], v2 = xr[tid + 512];
    float mean = blk_sum(v0 + v1 + v2, sred, tid) * (1.0f / DIMN);
    float d0 = v0 - mean, d1 = v1 - mean, d2 = v2 - mean;
    float var = blk_sum(d0 * d0 + d1 * d1 + d2 * d2, sred, tid) * (1.0f / DIMN);
    float inv = rsqrtf(var + 1e-5f);
    float o0 = d0 * inv * g[tid]       + b[tid];
    float o1 = d1 * inv * g[tid + 256] + b[tid + 256];
    float o2 = d2 * inv * g[tid + 512] + b[tid + 512];
    float tot = blk_sum(o0 + o1 + o2, sred, tid);
    if (tid == 0) s0[r] = tot;
    __half h, l;
    size_t base = (size_t)r * DIMN;
    split1(o0, h, l); ohi[base + tid]       = h; olo[base + tid]       = l;
    split1(o1, h, l); ohi[base + tid + 256] = h; olo[base + tid + 256] = l;
    split1(o2, h, l); ohi[base + tid + 512] = h; olo[base + tid + 512] = l;
}

// ---------------- rowsum ----------------
__global__ void rowsum_kernel(const __half* __restrict__ hi, const __half* __restrict__ lo,
                              float* __restrict__ s0, int K) {
    int r = blockIdx.x;
    int tid = threadIdx.x;
    __shared__ float sred[8];
    float s = 0.f;
    for (int k = tid * 4; k < K; k += 1024) {
        float2 h2 = __half22float2(*(const __half2*)(hi + (size_t)r * K + k));
        float2 h3 = __half22float2(*(const __half2*)(hi + (size_t)r * K + k + 2));
        float2 l2 = __half22float2(*(const __half2*)(lo + (size_t)r * K + k));
        float2 l3 = __half22float2(*(const __half2*)(lo + (size_t)r * K + k + 2));
        s += h2.x + h2.y + h3.x + h3.y + l2.x + l2.y + l3.x + l3.y;
    }
    float tot = blk_sum(s, sred, tid);
    if (tid == 0) s0[r] = tot;
}

// ---------------- split-K combine: x[r][n] += epilogue(sum partials) ----------------
template<int NPART, int GHOST>
__global__ void __launch_bounds__(192)
combine_kernel(const float* __restrict__ part,
               const float* __restrict__ bias, const float* __restrict__ scale,
               const float* __restrict__ S0, const float* __restrict__ lutp,
               float* __restrict__ x) {
    int r = blockIdx.x;
    int n = threadIdx.x * 4;             // 192 threads x 4 = 768
    size_t off = (size_t)r * DIMN + n;
    float4 s = *(const float4*)(part + off);
    #pragma unroll
    for (int p = 1; p < NPART; p++) {
        float4 q = *(const float4*)(part + (size_t)p * BT * DIMN + off);
        s.x += q.x; s.y += q.y; s.z += q.z; s.w += q.w;
    }
    float4 xo = *(float4*)(x + off);
    if (GHOST) {
        float L0 = __ldg(lutp), L255 = __ldg(lutp + 255);
        float c0f = L0, c1f = (L255 - L0) * (1.0f / 255.0f);
        float s0v = S0[r];
        float4 sc = *(const float4*)(scale + n);
        xo.x += (c1f * s.x + c0f * s0v) * sc.x;
        xo.y += (c1f * s.y + c0f * s0v) * sc.y;
        xo.z += (c1f * s.z + c0f * s0v) * sc.z;
        xo.w += (c1f * s.w + c0f * s0v) * sc.w;
    } else {
        float4 bv = *(const float4*)(bias + n);
        xo.x += s.x + bv.x; xo.y += s.y + bv.y;
        xo.z += s.z + bv.z; xo.w += s.w + bv.w;
    }
    *(float4*)(x + off) = xo;
}

// ---------------- flash attention (float4 + swizzle) ----------------
__global__ void __launch_bounds__(256)
flash_attn(const float* __restrict__ qkv,
           __half* __restrict__ ohi, __half* __restrict__ olo) {
    extern __shared__ float smf[];
    float* Qs = smf;
    float* Ks = Qs + 64 * 64;
    float* Vs = Ks + 64 * 64;
    float* Ps = Vs + 64 * 64;

    int qt = blockIdx.x, h = blockIdx.y, b = blockIdx.z;
    int tid = threadIdx.x;
    int ty = tid >> 4, tx = tid & 15;
    int q0 = qt * QT;

    for (int i = tid; i < QT * 16; i += 256) {
        int r = i >> 4, c4 = (i & 15) * 4;
        const float* src = qkv + ((size_t)(b * SEQ + q0 + r)) * QKVW + h * HD + c4;
        float4 v = *(const float4*)src;
        v.x *= 0.125f; v.y *= 0.125f; v.z *= 0.125f; v.w *= 0.125f;
        *(float4*)&Qs[swz(r, c4)] = v;
    }

    float m[4], l[4], O[4][4];
    #pragma unroll
    for (int i = 0; i < 4; i++) {
        m[i] = -1e30f; l[i] = 0.f;
        #pragma unroll
        for (int j = 0; j < 4; j++) O[i][j] = 0.f;
    }
    __syncthreads();

    for (int kt = 0; kt <= qt; kt++) {
        int k0 = kt * KT;
        for (int i = tid; i < KT * 16; i += 256) {
            int r = i >> 4, c4 = (i & 15) * 4;
            size_t rowb = ((size_t)(b * SEQ + k0 + r)) * QKVW + h * HD + c4;
            *(float4*)&Ks[swz(r, c4)] = *(const float4*)(qkv + rowb + DIMN);
            *(float4*)&Vs[swz(r, c4)] = *(const float4*)(qkv + rowb + 2 * DIMN);
        }
        __syncthreads();

        float s[4][4];
        #pragma unroll
        for (int i = 0; i < 4; i++)
            #pragma unroll
            for (int j = 0; j < 4; j++) s[i][j] = 0.f;
        #pragma unroll 4
        for (int d4 = 0; d4 < HD; d4 += 4) {
            float4 qv[4], kv[4];
            #pragma unroll
            for (int i = 0; i < 4; i++) qv[i] = *(const float4*)&Qs[swz(ty * 4 + i, d4)];
            #pragma unroll
            for (int j = 0; j < 4; j++) kv[j] = *(const float4*)&Ks[swz(tx * 4 + j, d4)];
            #pragma unroll
            for (int i = 0; i < 4; i++)
                #pragma unroll
                for (int j = 0; j < 4; j++) {
                    s[i][j] = fmaf(qv[i].x, kv[j].x, s[i][j]);
                    s[i][j] = fmaf(qv[i].y, kv[j].y, s[i][j]);
                    s[i][j] = fmaf(qv[i].z, kv[j].z, s[i][j]);
                    s[i][j] = fmaf(qv[i].w, kv[j].w, s[i][j]);
                }
        }
        if (kt == qt) {
            #pragma unroll
            for (int i = 0; i < 4; i++)
                #pragma unroll
                for (int j = 0; j < 4; j++)
                    if (k0 + tx * 4 + j > q0 + ty * 4 + i) s[i][j] = -1e30f;
        }

        float mt[4];
        #pragma unroll
        for (int i = 0; i < 4; i++)
            mt[i] = fmaxf(fmaxf(s[i][0], s[i][1]), fmaxf(s[i][2], s[i][3]));
        #pragma unroll
        for (int o = 1; o < 16; o <<= 1)
            #pragma unroll
            for (int i = 0; i < 4; i++)
                mt[i] = fmaxf(mt[i], __shfl_xor_sync(0xffffffffu, mt[i], o));

        float ps[4];
        #pragma unroll
        for (int i = 0; i < 4; i++) {
            float mn = fmaxf(m[i], mt[i]);
            float sc = __expf(m[i] - mn);
            m[i] = mn;
            l[i] *= sc;
            float4 p4;
            p4.x = __expf(s[i][0] - mn);
            p4.y = __expf(s[i][1] - mn);
            p4.z = __expf(s[i][2] - mn);
            p4.w = __expf(s[i][3] - mn);
            *(float4*)&Ps[swz(ty * 4 + i, tx * 4)] = p4;
            ps[i] = p4.x + p4.y + p4.z + p4.w;
            #pragma unroll
            for (int j = 0; j < 4; j++) O[i][j] *= sc;
        }
        #pragma unroll
        for (int o = 1; o < 16; o <<= 1)
            #pragma unroll
            for (int i = 0; i < 4; i++)
                ps[i] += __shfl_xor_sync(0xffffffffu, ps[i], o);
        #pragma unroll
        for (int i = 0; i < 4; i++) l[i] += ps[i];
        __syncthreads();

        #pragma unroll 4
        for (int k4 = 0; k4 < KT; k4 += 4) {
            float4 pv[4], vv[4];
            #pragma unroll
            for (int i = 0; i < 4; i++) pv[i] = *(const float4*)&Ps[swz(ty * 4 + i, k4)];
            #pragma unroll
            for (int kk = 0; kk < 4; kk++) vv[kk] = *(const float4*)&Vs[swz(k4 + kk, tx * 4)];
            #pragma unroll
            for (int i = 0; i < 4; i++) {
                O[i][0] = fmaf(pv[i].x, vv[0].x, O[i][0]);
                O[i][1] = fmaf(pv[i].x, vv[0].y, O[i][1]);
                O[i][2] = fmaf(pv[i].x, vv[0].z, O[i][2]);
                O[i][3] = fmaf(pv[i].x, vv[0].w, O[i][3]);
                O[i][0] = fmaf(pv[i].y, vv[1].x, O[i][0]);
                O[i][1] = fmaf(pv[i].y, vv[1].y, O[i][1]);
                O[i][2] = fmaf(pv[i].y, vv[1].z, O[i][2]);
                O[i][3] = fmaf(pv[i].y, vv[1].w, O[i][3]);
                O[i][0] = fmaf(pv[i].z, vv[2].x, O[i][0]);
                O[i][1] = fmaf(pv[i].z, vv[2].y, O[i][1]);
                O[i][2] = fmaf(pv[i].z, vv[2].z, O[i][2]);
                O[i][3] = fmaf(pv[i].z, vv[2].w, O[i][3]);
                O[i][0] = fmaf(pv[i].w, vv[3].x, O[i][0]);
                O[i][1] = fmaf(pv[i].w, vv[3].y, O[i][1]);
                O[i][2] = fmaf(pv[i].w, vv[3].z, O[i][2]);
                O[i][3] = fmaf(pv[i].w, vv[3].w, O[i][3]);
            }
        }
        __syncthreads();
    }

    #pragma unroll
    for (int i = 0; i < 4; i++) {
        float inv = 1.0f / l[i];
        size_t base = ((size_t)(b * SEQ + q0 + ty * 4 + i)) * DIMN + h * HD + tx * 4;
        #pragma unroll
        for (int j = 0; j < 4; j++) {
            float val = O[i][j] * inv;
            __half hh, ll; split1(val, hh, ll);
            ohi[base + j] = hh; olo[base + j] = ll;
        }
    }
}

// ---------------- HMMA GEMM (with optional split-K) ----------------
template<int GHOST, int ALO, int BIAS, int GELU, int RESID, int OUTSPLIT, int SPLITK>
__global__ void __launch_bounds__(256, 2)
hgemm(const __half* __restrict__ Ahi, const __half* __restrict__ Alo,
      const __half* __restrict__ Bhi, const __half* __restrict__ Blo,
      const float* __restrict__ bias, const float* __restrict__ scale,
      const float* __restrict__ S0, const float* __restrict__ lutp,
      const float* __restrict__ resid,
      float* __restrict__ C, __half* __restrict__ Ohi, __half* __restrict__ Olo,
      int M, int N, int K) {
    constexpr int BK     = GHOST ? 64 : 32;
    constexpr int ROWB   = GHOST ? 144 : 80;
    constexpr int PLANE  = GHOST ? 18432 : 10240;
    constexpr int APL    = 1 + ALO;
    constexpr int PLANES = APL + (GHOST ? 1 : 2);
    constexpr int STAGE_B = PLANES * PLANE;
    constexpr int KS_N   = BK / 16;
    constexpr int CHSH   = GHOST ? 3 : 2;
    constexpr int REPS   = GHOST ? 4 : 2;

    extern __shared__ __align__(128) char sm[];
    uint32_t smb = smem_u32(sm);

    int tid = threadIdx.x, wid = tid >> 5, lane = tid & 31;
    int grp = lane >> 2, tg = lane & 3;
    int wm = (wid & 1) * 64;
    int wn = (wid >> 1) * 32;
    int bm = blockIdx.x * 128;
    int bn = blockIdx.y * 128;
    int kb0 = (SPLITK > 1) ? (int)blockIdx.z * (K / SPLITK) : 0;

    float acc[16][4];
    #pragma unroll
    for (int i = 0; i < 16; i++)
        #pragma unroll
        for (int e = 0; e < 4; e++) acc[i][e] = 0.f;

    int nch = (K / SPLITK) / BK;

    auto issue = [&](int c) {
        uint32_t sb = smb + (uint32_t)(c & 1) * STAGE_B;
        int kb = kb0 + c * BK;
        #pragma unroll
        for (int rep = 0; rep < REPS; rep++) {
            int cid = tid + rep * 256;
            int row = cid >> CHSH, ch = cid & ((1 << CHSH) - 1);
            uint32_t doff = (uint32_t)(row * ROWB + ch * 16);
            size_t ga = (size_t)(bm + row) * K + kb + ch * 8;
            cp16(sb + doff, Ahi + ga);
            if (ALO) cp16(sb + PLANE + doff, Alo + ga);
            int br = bn + row; if (br >= N) br = N - 1;
            size_t gb = (size_t)br * K + kb + ch * 8;
            cp16(sb + APL * PLANE + doff, Bhi + gb);
            if (!GHOST) cp16(sb + (APL + 1) * PLANE + doff, Blo + gb);
        }
        CP_COMMIT();
    };

    issue(0);
    if (nch > 1) issue(1);

    uint32_t aoffL = (uint32_t)((wm + (lane & 15)) * ROWB + ((lane >> 4) << 4));
    uint32_t boffL = (uint32_t)((wn + (lane & 7) + ((lane >> 4) << 3)) * ROWB
                                + (((lane >> 3) & 1) << 4));

    for (int c = 0; c < nch; c++) {
        if (c + 1 < nch) CP_WAIT1(); else CP_WAIT0();
        __syncthreads();

        uint32_t sb = smb + (uint32_t)(c & 1) * STAGE_B;
        #pragma unroll
        for (int ks = 0; ks < KS_N; ks++) {
            uint32_t ao = sb + aoffL + ks * 32;
            uint32_t bo = sb + APL * PLANE + boffL + ks * 32;
            unsigned ah[4][4], al[4][4], bh[4][2], bl[4][2];
            #pragma unroll
            for (int i = 0; i < 4; i++) {
                LDSM4(ah[i][0], ah[i][1], ah[i][2], ah[i][3], ao + i * 16 * ROWB);
                if (ALO)
                    LDSM4(al[i][0], al[i][1], al[i][2], al[i][3], ao + PLANE + i * 16 * ROWB);
            }
            #pragma unroll
            for (int j2 = 0; j2 < 2; j2++) {
                unsigned r0, r1, r2, r3;
                LDSM4(r0, r1, r2, r3, bo + j2 * 16 * ROWB);
                bh[j2 * 2][0] = r0; bh[j2 * 2][1] = r1;
                bh[j2 * 2 + 1][0] = r2; bh[j2 * 2 + 1][1] = r3;
                if (!GHOST) {
                    LDSM4(r0, r1, r2, r3, bo + PLANE + j2 * 16 * ROWB);
                    bl[j2 * 2][0] = r0; bl[j2 * 2][1] = r1;
                    bl[j2 * 2 + 1][0] = r2; bl[j2 * 2 + 1][1] = r3;
                }
            }
            #pragma unroll
            for (int i = 0; i < 4; i++)
                #pragma unroll
                for (int j = 0; j < 4; j++) {
                    float* a4 = acc[i * 4 + j];
                    MMA16816(a4, ah[i][0], ah[i][1], ah[i][2], ah[i][3], bh[j][0], bh[j][1]);
                    if (ALO)
                        MMA16816(a4, al[i][0], al[i][1], al[i][2], al[i][3], bh[j][0], bh[j][1]);
                    if (!GHOST)
                        MMA16816(a4, ah[i][0], ah[i][1], ah[i][2], ah[i][3], bl[j][0], bl[j][1]);
                }
        }
        __syncthreads();
        if (c + 2 < nch) issue(c + 2);
    }

    // ---- epilogue ----
    if (SPLITK > 1) {
        float* Cp = C + (size_t)blockIdx.z * M * N;
        #pragma unroll
        for (int i = 0; i < 4; i++) {
            int mA = bm + wm + i * 16 + grp;
            #pragma unroll
            for (int j = 0; j < 4; j++) {
                int n0 = bn + wn + j * 8 + 2 * tg;
                #pragma unroll
                for (int e = 0; e < 4; e++) {
                    int m = mA + ((e >= 2) ? 8 : 0);
                    int n = n0 + (e & 1);
                    Cp[(size_t)m * N + n] = acc[i * 4 + j][e];
                }
            }
        }
        return;
    }

    float c0f = 0.f, c1f = 0.f;
    if (GHOST) {
        float L0 = __ldg(lutp), L255 = __ldg(lutp + 255);
        c0f = L0;
        c1f = (L255 - L0) * (1.0f / 255.0f);
    }
    #pragma unroll
    for (int i = 0; i < 4; i++) {
        int mA = bm + wm + i * 16 + grp;
        float s0a = 0.f, s0b = 0.f;
        if (GHOST) { s0a = S0[mA]; s0b = S0[mA + 8]; }
        #pragma unroll
        for (int j = 0; j < 4; j++) {
            int n0 = bn + wn + j * 8 + 2 * tg;
            #pragma unroll
            for (int e = 0; e < 4; e++) {
                int m = mA + ((e >= 2) ? 8 : 0);
                int n = n0 + (e & 1);
                if (n < N) {
                    float t = acc[i * 4 + j][e];
                    if (GHOST) t = (c1f * t + c0f * ((e >= 2) ? s0b : s0a)) * scale[n];
                    if (BIAS)  t += bias[n];
                    if (GELU)  t = gelu_tanh(t);
                    if (RESID) t += resid[(size_t)m * N + n];
                    if (OUTSPLIT) {
                        __half hh, ll; split1(t, hh, ll);
                        Ohi[(size_t)m * N + n] = hh;
                        Olo[(size_t)m * N + n] = ll;
                    } else {
                        C[(size_t)m * N + n] = t;
                    }
                }
            }
        }
    }
}

// ---------------- launch ----------------
extern "C" void kernel_launch(void* const* d_in, const int* in_sizes, int n_in,
                              void* d_out, int out_size) {
    const float* lut        = (const float*)d_in[0];
    const float* tok_emb    = (const float*)d_in[1];
    const float* pos_emb    = (const float*)d_in[2];
    const float* ln1_g      = (const float*)d_in[3];
    const float* ln1_b      = (const float*)d_in[4];
    const float* in_w       = (const float*)d_in[5];
    const float* in_b       = (const float*)d_in[6];
    const float* out_w      = (const float*)d_in[7];
    const float* out_b      = (const float*)d_in[8];
    const float* ln2_g      = (const float*)d_in[9];
    const float* ln2_b      = (const float*)d_in[10];
    const float* mlp1_scale = (const float*)d_in[11];
    const float* mlp2_scale = (const float*)d_in[12];
    const float* lnf_g      = (const float*)d_in[13];
    const float* lnf_b      = (const float*)d_in[14];
    const float* head_scale = (const float*)d_in[15];
    const int*   mlp1_idx   = (const int*)d_in[16];
    const int*   mlp2_idx   = (const int*)d_in[17];
    const int*   head_idx   = (const int*)d_in[18];
    const int*   idx        = (const int*)d_in[19];
    float* out = (float*)d_out;

    float *x, *qkv, *part, *s0_ln, *s0_mlp;
    __half *ln_hi, *ln_lo, *att_hi, *att_lo, *mlp_hi, *mlp_lo;
    __half *wq_hi, *wq_lo, *wp_hi, *wp_lo, *w1_i, *w2_i, *wh_i;
    cudaGetSymbolAddress((void**)&x,      g_x);
    cudaGetSymbolAddress((void**)&qkv,    g_qkv);
    cudaGetSymbolAddress((void**)&part,   g_part);
    cudaGetSymbolAddress((void**)&s0_ln,  g_s0_ln);
    cudaGetSymbolAddress((void**)&s0_mlp, g_s0_mlp);
    cudaGetSymbolAddress((void**)&ln_hi,  g_ln_hi);
    cudaGetSymbolAddress((void**)&ln_lo,  g_ln_lo);
    cudaGetSymbolAddress((void**)&att_hi, g_att_hi);
    cudaGetSymbolAddress((void**)&att_lo, g_att_lo);
    cudaGetSymbolAddress((void**)&mlp_hi, g_mlp_hi);
    cudaGetSymbolAddress((void**)&mlp_lo, g_mlp_lo);
    cudaGetSymbolAddress((void**)&wq_hi,  w_qkv_hi);
    cudaGetSymbolAddress((void**)&wq_lo,  w_qkv_lo);
    cudaGetSymbolAddress((void**)&wp_hi,  w_proj_hi);
    cudaGetSymbolAddress((void**)&wp_lo,  w_proj_lo);
    cudaGetSymbolAddress((void**)&w1_i,   w_mlp1_i);
    cudaGetSymbolAddress((void**)&w2_i,   w_mlp2_i);
    cudaGetSymbolAddress((void**)&wh_i,   w_head_i);

    static int attr_done = 0;
    if (!attr_done) {
        cudaFuncSetAttribute(hgemm<0,1,1,0,0,0,1>, cudaFuncAttributeMaxDynamicSharedMemorySize, SM_DENSE);
        cudaFuncSetAttribute(hgemm<0,1,0,0,0,0,2>, cudaFuncAttributeMaxDynamicSharedMemorySize, SM_DENSE);
        cudaFuncSetAttribute(hgemm<1,1,0,1,0,1,1>, cudaFuncAttributeMaxDynamicSharedMemorySize, SM_GHOST);
        cudaFuncSetAttribute(hgemm<1,1,0,0,0,0,4>, cudaFuncAttributeMaxDynamicSharedMemorySize, SM_GHOST);
        cudaFuncSetAttribute(hgemm<1,0,0,0,0,0,1>, cudaFuncAttributeMaxDynamicSharedMemorySize, SM_HEAD);
        cudaFuncSetAttribute(flash_attn,           cudaFuncAttributeMaxDynamicSharedMemorySize, SM_ATTN);
        attr_done = 1;
    }

    conv_all<<<NB0 + NB1 + NB2 + NB3 + NB4, 256>>>(
        in_w, out_w, mlp1_idx, mlp2_idx, head_idx,
        wq_hi, wq_lo, wp_hi, wp_lo, w1_i, w2_i, wh_i);

    embed_kernel<<<BT, 256>>>(idx, tok_emb, pos_emb, x);

    for (int l = 0; l < NL; l++) {
        ln_kernel<<<BT, 256>>>(x, ln1_g + l * DIMN, ln1_b + l * DIMN, ln_hi, ln_lo, s0_ln);
        {
            dim3 grid(BT / 128, QKVW / 128);          // 16 x 18
            hgemm<0,1,1,0,0,0,1><<<grid, 256, SM_DENSE>>>(
                ln_hi, ln_lo,
                wq_hi + (size_t)l * QKVW * DIMN, wq_lo + (size_t)l * QKVW * DIMN,
                in_b + (size_t)l * QKVW, nullptr, nullptr, nullptr, nullptr,
                qkv, nullptr, nullptr, BT, QKVW, DIMN);
        }
        {
            dim3 grid(SEQ / QT, NH, BATCH);
            flash_attn<<<grid, 256, SM_ATTN>>>(qkv, att_hi, att_lo);
        }
        {
            // proj: split-K=2 partials + combine (dense)
            dim3 grid(BT / 128, DIMN / 128, 2);       // 16 x 6 x 2
            hgemm<0,1,0,0,0,0,2><<<grid, 256, SM_DENSE>>>(
                att_hi, att_lo,
                wp_hi + (size_t)l * DIMN * DIMN, wp_lo + (size_t)l * DIMN * DIMN,
                nullptr, nullptr, nullptr, nullptr, nullptr,
                part, nullptr, nullptr, BT, DIMN, DIMN);
            combine_kernel<2,0><<<BT, 192>>>(part, out_b + (size_t)l * DIMN,
                                             nullptr, nullptr, nullptr, x);
        }
        ln_kernel<<<BT, 256>>>(x, ln2_g + l * DIMN, ln2_b + l * DIMN, ln_hi, ln_lo, s0_ln);
        {
            dim3 grid(BT / 128, HID / 128);           // 16 x 24
            hgemm<1,1,0,1,0,1,1><<<grid, 256, SM_GHOST>>>(
                ln_hi, ln_lo,
                w1_i + (size_t)l * HID * DIMN, nullptr,
                nullptr, mlp1_scale + (size_t)l * HID, s0_ln, lut, nullptr,
                nullptr, mlp_hi, mlp_lo, BT, HID, DIMN);
        }
        rowsum_kernel<<<BT, 256>>>(mlp_hi, mlp_lo, s0_mlp, HID);
        {
            // mlp2: split-K=4 partials + combine (ghost)
            dim3 grid(BT / 128, DIMN / 128, 4);       // 16 x 6 x 4
            hgemm<1,1,0,0,0,0,4><<<grid, 256, SM_GHOST>>>(
                mlp_hi, mlp_lo,
                w2_i + (size_t)l * DIMN * HID, nullptr,
                nullptr, nullptr, nullptr, nullptr, nullptr,
                part, nullptr, nullptr, BT, DIMN, HID);
            combine_kernel<4,1><<<BT, 192>>>(part, nullptr,
                                             mlp2_scale + (size_t)l * DIMN, s0_mlp, lut, x);
        }
    }

    ln_kernel<<<BT, 256>>>(x, lnf_g, lnf_b, ln_hi, ln_lo, s0_ln);

    {
        dim3 grid(BT / 128, (VOCAB + 127) / 128);     // 16 x 393
        hgemm<1,0,0,0,0,0,1><<<grid, 256, SM_HEAD>>>(
            ln_hi, nullptr, wh_i, nullptr,
            nullptr, head_scale, s0_ln, lut, nullptr,
            out, nullptr, nullptr, BT, VOCAB, DIMN);
    }
}

// round 17
// speedup vs baseline: 1.0982x; 1.0250x over previous
#include <cuda_runtime.h>
#include <cuda_fp16.h>
#include <cstdint>
#include <math.h>

// ---------------- problem constants ----------------
#define DIMN 768
#define NL   13
#define NH   12
#define HD   64
#define VOCAB 50257
#define SEQ  512
#define BATCH 4
#define HID  3072
#define BT   (BATCH*SEQ)      // 2048
#define QKVW (3*DIMN)         // 2304

// ---------------- gemm config ----------------
#define SM_DENSE (2 * 4 * 10240)   // 81920
#define SM_GHOST (2 * 3 * 18432)   // 110592
#define SM_HEAD  (2 * 2 * 18432)   // 73728

// ---------------- flash attention config ----------------
#define QT 64
#define KT 64
#define SM_ATTN (4 * 64 * 64 * 4)  // 65536

// ---------------- scratch ----------------
__device__ float  g_x   [(size_t)BT*DIMN];
__device__ float  g_qkv [(size_t)BT*QKVW];
__device__ float  g_part[(size_t)4*BT*DIMN];
__device__ float  g_s0_ln [BT];
__device__ float  g_s0_mlp[BT];
__device__ __half g_ln_hi [(size_t)BT*DIMN];
__device__ __half g_ln_lo [(size_t)BT*DIMN];
__device__ __half g_att_hi[(size_t)BT*DIMN];
__device__ __half g_att_lo[(size_t)BT*DIMN];
__device__ __half g_mlp_hi[(size_t)BT*HID];
__device__ __half g_mlp_lo[(size_t)BT*HID];
__device__ __half w_qkv_hi [(size_t)NL*QKVW*DIMN];
__device__ __half w_qkv_lo [(size_t)NL*QKVW*DIMN];
__device__ __half w_proj_hi[(size_t)NL*DIMN*DIMN];
__device__ __half w_proj_lo[(size_t)NL*DIMN*DIMN];
__device__ __half w_mlp1_i [(size_t)NL*HID*DIMN];
__device__ __half w_mlp2_i [(size_t)NL*DIMN*HID];
__device__ __half w_head_i [(size_t)VOCAB*DIMN];

// ---------------- helpers ----------------
__device__ __forceinline__ void split1(float v, __half& h, __half& l) {
    h = __float2half_rn(v);
    l = __float2half_rn(v - __half2float(h));
}
__device__ __forceinline__ float gelu_tanh(float x) {
    float x3 = x * x * x;
    return 0.5f * x * (1.0f + tanhf(0.7978845608028654f * (x + 0.044715f * x3)));
}
__device__ __forceinline__ uint32_t smem_u32(const void* p) {
    uint32_t a;
    asm("{ .reg .u64 t; cvta.to.shared.u64 t, %1; cvt.u32.u64 %0, t; }" : "=r"(a) : "l"(p));
    return a;
}
__device__ __forceinline__ void cp16(uint32_t dst, const void* src) {
    asm volatile("cp.async.cg.shared.global [%0], [%1], 16;" :: "r"(dst), "l"(src));
}
#define CP_COMMIT() asm volatile("cp.async.commit_group;" ::: "memory")
#define CP_WAIT1()  asm volatile("cp.async.wait_group 1;" ::: "memory")
#define CP_WAIT0()  asm volatile("cp.async.wait_group 0;" ::: "memory")

#define LDSM4(r0, r1, r2, r3, addr)                                           \
    asm volatile("ldmatrix.sync.aligned.m8n8.x4.shared.b16 {%0,%1,%2,%3}, [%4];" \
        : "=r"(r0), "=r"(r1), "=r"(r2), "=r"(r3) : "r"(addr))

#define MMA16816(c, a0, a1, a2, a3, b0, b1)                                   \
    asm volatile(                                                             \
        "mma.sync.aligned.m16n8k16.row.col.f32.f16.f16.f32 "                  \
        "{%0,%1,%2,%3}, {%4,%5,%6,%7}, {%8,%9}, {%0,%1,%2,%3};"               \
        : "+f"((c)[0]), "+f"((c)[1]), "+f"((c)[2]), "+f"((c)[3])              \
        : "r"(a0), "r"(a1), "r"(a2), "r"(a3), "r"(b0), "r"(b1))

// block reduce, 256 threads (8 warps)
__device__ __forceinline__ float blk_sum(float v, float* sred, int tid) {
    #pragma unroll
    for (int o = 16; o > 0; o >>= 1) v += __shfl_xor_sync(0xffffffffu, v, o);
    if ((tid & 31) == 0) sred[tid >> 5] = v;
    __syncthreads();
    float t = sred[0] + sred[1] + sred[2] + sred[3]
            + sred[4] + sred[5] + sred[6] + sred[7];
    __syncthreads();
    return t;
}
// block reduce, 192 threads (6 warps)
__device__ __forceinline__ float blk_sum6(float v, float* sred, int tid) {
    #pragma unroll
    for (int o = 16; o > 0; o >>= 1) v += __shfl_xor_sync(0xffffffffu, v, o);
    if ((tid & 31) == 0) sred[tid >> 5] = v;
    __syncthreads();
    float t = sred[0] + sred[1] + sred[2] + sred[3] + sred[4] + sred[5];
    __syncthreads();
    return t;
}

// swizzled 64x64 float tile addressing
__device__ __forceinline__ int swz(int r, int c) {
    return r * 64 + ((((c >> 2) ^ ((r >> 2) & 15)) << 2) | (c & 3));
}

// ---------------- merged conversion ----------------
#define N0 ((size_t)NL*QKVW*DIMN)
#define N1 ((size_t)NL*DIMN*DIMN)
#define N2 ((size_t)NL*HID*DIMN)
#define N3 ((size_t)NL*DIMN*HID)
#define N4 ((size_t)VOCAB*DIMN)
#define NB0 ((unsigned)(N0/1024))
#define NB1 ((unsigned)(N1/1024))
#define NB2 ((unsigned)(N2/2048))
#define NB3 ((unsigned)(N3/2048))
#define NB4 ((unsigned)((N4+2047)/2048))

__device__ __forceinline__ void conv_w_body(const float* __restrict__ w,
                                            __half* __restrict__ hi, __half* __restrict__ lo,
                                            size_t n, unsigned blk) {
    size_t i = ((size_t)blk * 256 + threadIdx.x) * 4;
    if (i >= n) return;
    float4 v = *(const float4*)(w + i);
    __half h[4], l[4];
    split1(v.x, h[0], l[0]); split1(v.y, h[1], l[1]);
    split1(v.z, h[2], l[2]); split1(v.w, h[3], l[3]);
    *(ushort4*)(hi + i) = make_ushort4(__half_as_ushort(h[0]), __half_as_ushort(h[1]),
                                       __half_as_ushort(h[2]), __half_as_ushort(h[3]));
    *(ushort4*)(lo + i) = make_ushort4(__half_as_ushort(l[0]), __half_as_ushort(l[1]),
                                       __half_as_ushort(l[2]), __half_as_ushort(l[3]));
}
__device__ __forceinline__ void conv_i_body(const int* __restrict__ idx,
                                            __half* __restrict__ o, size_t n, unsigned blk) {
    size_t i = ((size_t)blk * 256 + threadIdx.x) * 8;
    if (i >= n) return;
    int4 a = *(const int4*)(idx + i);
    int4 b = *(const int4*)(idx + i + 4);
    int id[8] = {a.x, a.y, a.z, a.w, b.x, b.y, b.z, b.w};
    ushort h[8];
    #pragma unroll
    for (int j = 0; j < 8; j++)
        h[j] = __half_as_ushort(__float2half_rn((float)id[j]));
    *(uint4*)(o + i) = *(uint4*)h;
}

__global__ void conv_all(const float* __restrict__ in_w,  const float* __restrict__ out_w,
                         const int* __restrict__ i1, const int* __restrict__ i2,
                         const int* __restrict__ ih,
                         __half* __restrict__ wq_hi_, __half* __restrict__ wq_lo_,
                         __half* __restrict__ wp_hi_, __half* __restrict__ wp_lo_,
                         __half* __restrict__ w1_, __half* __restrict__ w2_,
                         __half* __restrict__ wh_) {
    unsigned b = blockIdx.x;
    if (b < NB0) { conv_w_body(in_w,  wq_hi_, wq_lo_, N0, b); return; }
    b -= NB0;
    if (b < NB1) { conv_w_body(out_w, wp_hi_, wp_lo_, N1, b); return; }
    b -= NB1;
    if (b < NB2) { conv_i_body(i1, w1_, N2, b); return; }
    b -= NB2;
    if (b < NB3) { conv_i_body(i2, w2_, N3, b); return; }
    b -= NB3;
    conv_i_body(ih, wh_, N4, b);
}

// ---------------- embedding ----------------
__global__ void embed_kernel(const int* __restrict__ idx, const float* __restrict__ tok,
                             const float* __restrict__ pos, float* __restrict__ x) {
    int r = blockIdx.x;
    int t = r % SEQ;
    int token = idx[r];
    const float* tr = tok + (size_t)token * DIMN;
    const float* pr = pos + (size_t)t * DIMN;
    float* xr = x + (size_t)r * DIMN;
    for (int d = threadIdx.x; d < DIMN; d += blockDim.x)
        xr[d] = tr[d] + pr[d];
}

// ---------------- standalone layernorm (layer 0 only) ----------------
__global__ void ln_kernel(const float* __restrict__ x, const float* __restrict__ g,
                          const float* __restrict__ b,
                          __half* __restrict__ ohi, __half* __restrict__ olo,
                          float* __restrict__ s0) {
    int r = blockIdx.x;
    int tid = threadIdx.x;
    const float* xr = x + (size_t)r * DIMN;
    __shared__ float sred[8];

    float v0 = xr[tid], v1 = xr[tid + 256], v2 = xr[tid + 512];
    float mean = blk_sum(v0 + v1 + v2, sred, tid) * (1.0f / DIMN);
    float d0 = v0 - mean, d1 = v1 - mean, d2 = v2 - mean;
    float var = blk_sum(d0 * d0 + d1 * d1 + d2 * d2, sred, tid) * (1.0f / DIMN);
    float inv = rsqrtf(var + 1e-5f);
    float o0 = d0 * inv * g[tid]       + b[tid];
    float o1 = d1 * inv * g[tid + 256] + b[tid + 256];
    float o2 = d2 * inv * g[tid + 512] + b[tid + 512];
    float tot = blk_sum(o0 + o1 + o2, sred, tid);
    if (tid == 0) s0[r] = tot;
    __half h, l;
    size_t base = (size_t)r * DIMN;
    split1(o0, h, l); ohi[base + tid]       = h; olo[base + tid]       = l;
    split1(o1, h, l); ohi[base + tid + 256] = h; olo[base + tid + 256] = l;
    split1(o2, h, l); ohi[base + tid + 512] = h; olo[base + tid + 512] = l;
}

// ---------------- fused split-K combine + residual + LayerNorm ----------------
// 192 threads, 1 block per row. Sums NPART partials, applies epilogue, updates x,
// then LayerNorms the new row into split fp16 planes + s0_out. Optionally zeroes s0z.
template<int NPART, int GHOST>
__global__ void __launch_bounds__(192)
combine_ln(const float* __restrict__ part,
           const float* __restrict__ bias, const float* __restrict__ scale,
           const float* __restrict__ S0in, const float* __restrict__ lutp,
           const float* __restrict__ g, const float* __restrict__ b,
           float* __restrict__ x,
           __half* __restrict__ ohi, __half* __restrict__ olo,
           float* __restrict__ s0_out, float* __restrict__ s0z) {
    int r = blockIdx.x;
    int tid = threadIdx.x;
    int n = tid * 4;
    size_t off = (size_t)r * DIMN + n;
    __shared__ float sred[6];

    float4 s = *(const float4*)(part + off);
    #pragma unroll
    for (int p = 1; p < NPART; p++) {
        float4 q = *(const float4*)(part + (size_t)p * BT * DIMN + off);
        s.x += q.x; s.y += q.y; s.z += q.z; s.w += q.w;
    }
    float4 xo = *(float4*)(x + off);
    if (GHOST) {
        float L0 = __ldg(lutp), L255 = __ldg(lutp + 255);
        float c0f = L0, c1f = (L255 - L0) * (1.0f / 255.0f);
        float s0v = S0in[r];
        float4 sc = *(const float4*)(scale + n);
        xo.x += (c1f * s.x + c0f * s0v) * sc.x;
        xo.y += (c1f * s.y + c0f * s0v) * sc.y;
        xo.z += (c1f * s.z + c0f * s0v) * sc.z;
        xo.w += (c1f * s.w + c0f * s0v) * sc.w;
    } else {
        float4 bv = *(const float4*)(bias + n);
        xo.x += s.x + bv.x; xo.y += s.y + bv.y;
        xo.z += s.z + bv.z; xo.w += s.w + bv.w;
    }
    *(float4*)(x + off) = xo;

    // LayerNorm on xo
    float mean = blk_sum6(xo.x + xo.y + xo.z + xo.w, sred, tid) * (1.0f / DIMN);
    float d0 = xo.x - mean, d1 = xo.y - mean, d2 = xo.z - mean, d3 = xo.w - mean;
    float var = blk_sum6(d0 * d0 + d1 * d1 + d2 * d2 + d3 * d3, sred, tid) * (1.0f / DIMN);
    float inv = rsqrtf(var + 1e-5f);
    float4 gv = *(const float4*)(g + n);
    float4 bv2 = *(const float4*)(b + n);
    float o0 = d0 * inv * gv.x + bv2.x;
    float o1 = d1 * inv * gv.y + bv2.y;
    float o2 = d2 * inv * gv.z + bv2.z;
    float o3 = d3 * inv * gv.w + bv2.w;
    float tot = blk_sum6(o0 + o1 + o2 + o3, sred, tid);
    if (tid == 0) {
        s0_out[r] = tot;
        if (s0z) s0z[r] = 0.f;
    }
    __half hh[4], ll[4];
    split1(o0, hh[0], ll[0]); split1(o1, hh[1], ll[1]);
    split1(o2, hh[2], ll[2]); split1(o3, hh[3], ll[3]);
    *(ushort4*)(ohi + off) = make_ushort4(__half_as_ushort(hh[0]), __half_as_ushort(hh[1]),
                                          __half_as_ushort(hh[2]), __half_as_ushort(hh[3]));
    *(ushort4*)(olo + off) = make_ushort4(__half_as_ushort(ll[0]), __half_as_ushort(ll[1]),
                                          __half_as_ushort(ll[2]), __half_as_ushort(ll[3]));
}

// ---------------- flash attention (float4 + swizzle, 3 CTAs/SM) ----------------
__global__ void __launch_bounds__(256, 3)
flash_attn(const float* __restrict__ qkv,
           __half* __restrict__ ohi, __half* __restrict__ olo) {
    extern __shared__ float smf[];
    float* Qs = smf;
    float* Ks = Qs + 64 * 64;
    float* Vs = Ks + 64 * 64;
    float* Ps = Vs + 64 * 64;

    int qt = blockIdx.x, h = blockIdx.y, b = blockIdx.z;
    int tid = threadIdx.x;
    int ty = tid >> 4, tx = tid & 15;
    int q0 = qt * QT;

    for (int i = tid; i < QT * 16; i += 256) {
        int r = i >> 4, c4 = (i & 15) * 4;
        const float* src = qkv + ((size_t)(b * SEQ + q0 + r)) * QKVW + h * HD + c4;
        float4 v = *(const float4*)src;
        v.x *= 0.125f; v.y *= 0.125f; v.z *= 0.125f; v.w *= 0.125f;
        *(float4*)&Qs[swz(r, c4)] = v;
    }

    float m[4], l[4], O[4][4];
    #pragma unroll
    for (int i = 0; i < 4; i++) {
        m[i] = -1e30f; l[i] = 0.f;
        #pragma unroll
        for (int j = 0; j < 4; j++) O[i][j] = 0.f;
    }
    __syncthreads();

    for (int kt = 0; kt <= qt; kt++) {
        int k0 = kt * KT;
        for (int i = tid; i < KT * 16; i += 256) {
            int r = i >> 4, c4 = (i & 15) * 4;
            size_t rowb = ((size_t)(b * SEQ + k0 + r)) * QKVW + h * HD + c4;
            *(float4*)&Ks[swz(r, c4)] = *(const float4*)(qkv + rowb + DIMN);
            *(float4*)&Vs[swz(r, c4)] = *(const float4*)(qkv + rowb + 2 * DIMN);
        }
        __syncthreads();

        float s[4][4];
        #pragma unroll
        for (int i = 0; i < 4; i++)
            #pragma unroll
            for (int j = 0; j < 4; j++) s[i][j] = 0.f;
        #pragma unroll 4
        for (int d4 = 0; d4 < HD; d4 += 4) {
            float4 qv[4], kv[4];
            #pragma unroll
            for (int i = 0; i < 4; i++) qv[i] = *(const float4*)&Qs[swz(ty * 4 + i, d4)];
            #pragma unroll
            for (int j = 0; j < 4; j++) kv[j] = *(const float4*)&Ks[swz(tx * 4 + j, d4)];
            #pragma unroll
            for (int i = 0; i < 4; i++)
                #pragma unroll
                for (int j = 0; j < 4; j++) {
                    s[i][j] = fmaf(qv[i].x, kv[j].x, s[i][j]);
                    s[i][j] = fmaf(qv[i].y, kv[j].y, s[i][j]);
                    s[i][j] = fmaf(qv[i].z, kv[j].z, s[i][j]);
                    s[i][j] = fmaf(qv[i].w, kv[j].w, s[i][j]);
                }
        }
        if (kt == qt) {
            #pragma unroll
            for (int i = 0; i < 4; i++)
                #pragma unroll
                for (int j = 0; j < 4; j++)
                    if (k0 + tx * 4 + j > q0 + ty * 4 + i) s[i][j] = -1e30f;
        }

        float mt[4];
        #pragma unroll
        for (int i = 0; i < 4; i++)
            mt[i] = fmaxf(fmaxf(s[i][0], s[i][1]), fmaxf(s[i][2], s[i][3]));
        #pragma unroll
        for (int o = 1; o < 16; o <<= 1)
            #pragma unroll
            for (int i = 0; i < 4; i++)
                mt[i] = fmaxf(mt[i], __shfl_xor_sync(0xffffffffu, mt[i], o));

        float ps[4];
        #pragma unroll
        for (int i = 0; i < 4; i++) {
            float mn = fmaxf(m[i], mt[i]);
            float sc = __expf(m[i] - mn);
            m[i] = mn;
            l[i] *= sc;
            float4 p4;
            p4.x = __expf(s[i][0] - mn);
            p4.y = __expf(s[i][1] - mn);
            p4.z = __expf(s[i][2] - mn);
            p4.w = __expf(s[i][3] - mn);
            *(float4*)&Ps[swz(ty * 4 + i, tx * 4)] = p4;
            ps[i] = p4.x + p4.y + p4.z + p4.w;
            #pragma unroll
            for (int j = 0; j < 4; j++) O[i][j] *= sc;
        }
        #pragma unroll
        for (int o = 1; o < 16; o <<= 1)
            #pragma unroll
            for (int i = 0; i < 4; i++)
                ps[i] += __shfl_xor_sync(0xffffffffu, ps[i], o);
        #pragma unroll
        for (int i = 0; i < 4; i++) l[i] += ps[i];
        __syncthreads();

        #pragma unroll 4
        for (int k4 = 0; k4 < KT; k4 += 4) {
            float4 pv[4], vv[4];
            #pragma unroll
            for (int i = 0; i < 4; i++) pv[i] = *(const float4*)&Ps[swz(ty * 4 + i, k4)];
            #pragma unroll
            for (int kk = 0; kk < 4; kk++) vv[kk] = *(const float4*)&Vs[swz(k4 + kk, tx * 4)];
            #pragma unroll
            for (int i = 0; i < 4; i++) {
                O[i][0] = fmaf(pv[i].x, vv[0].x, O[i][0]);
                O[i][1] = fmaf(pv[i].x, vv[0].y, O[i][1]);
                O[i][2] = fmaf(pv[i].x, vv[0].z, O[i][2]);
                O[i][3] = fmaf(pv[i].x, vv[0].w, O[i][3]);
                O[i][0] = fmaf(pv[i].y, vv[1].x, O[i][0]);
                O[i][1] = fmaf(pv[i].y, vv[1].y, O[i][1]);
                O[i][2] = fmaf(pv[i].y, vv[1].z, O[i][2]);
                O[i][3] = fmaf(pv[i].y, vv[1].w, O[i][3]);
                O[i][0] = fmaf(pv[i].z, vv[2].x, O[i][0]);
                O[i][1] = fmaf(pv[i].z, vv[2].y, O[i][1]);
                O[i][2] = fmaf(pv[i].z, vv[2].z, O[i][2]);
                O[i][3] = fmaf(pv[i].z, vv[2].w, O[i][3]);
                O[i][0] = fmaf(pv[i].w, vv[3].x, O[i][0]);
                O[i][1] = fmaf(pv[i].w, vv[3].y, O[i][1]);
                O[i][2] = fmaf(pv[i].w, vv[3].z, O[i][2]);
                O[i][3] = fmaf(pv[i].w, vv[3].w, O[i][3]);
            }
        }
        __syncthreads();
    }

    #pragma unroll
    for (int i = 0; i < 4; i++) {
        float inv = 1.0f / l[i];
        size_t base = ((size_t)(b * SEQ + q0 + ty * 4 + i)) * DIMN + h * HD + tx * 4;
        #pragma unroll
        for (int j = 0; j < 4; j++) {
            float val = O[i][j] * inv;
            __half hh, ll; split1(val, hh, ll);
            ohi[base + j] = hh; olo[base + j] = ll;
        }
    }
}

// ---------------- HMMA GEMM (split-K, optional fused rowsum) ----------------
template<int GHOST, int ALO, int BIAS, int GELU, int RESID, int OUTSPLIT, int SPLITK, int ROWSUM>
__global__ void __launch_bounds__(256, 2)
hgemm(const __half* __restrict__ Ahi, const __half* __restrict__ Alo,
      const __half* __restrict__ Bhi, const __half* __restrict__ Blo,
      const float* __restrict__ bias, const float* __restrict__ scale,
      const float* __restrict__ S0, const float* __restrict__ lutp,
      const float* __restrict__ resid,
      float* __restrict__ C, __half* __restrict__ Ohi, __half* __restrict__ Olo,
      float* __restrict__ s0out,
      int M, int N, int K) {
    constexpr int BK     = GHOST ? 64 : 32;
    constexpr int ROWB   = GHOST ? 144 : 80;
    constexpr int PLANE  = GHOST ? 18432 : 10240;
    constexpr int APL    = 1 + ALO;
    constexpr int PLANES = APL + (GHOST ? 1 : 2);
    constexpr int STAGE_B = PLANES * PLANE;
    constexpr int KS_N   = BK / 16;
    constexpr int CHSH   = GHOST ? 3 : 2;
    constexpr int REPS   = GHOST ? 4 : 2;

    extern __shared__ __align__(128) char sm[];
    uint32_t smb = smem_u32(sm);

    int tid = threadIdx.x, wid = tid >> 5, lane = tid & 31;
    int grp = lane >> 2, tg = lane & 3;
    int wm = (wid & 1) * 64;
    int wn = (wid >> 1) * 32;
    int bm = blockIdx.x * 128;
    int bn = blockIdx.y * 128;
    int kb0 = (SPLITK > 1) ? (int)blockIdx.z * (K / SPLITK) : 0;

    float acc[16][4];
    #pragma unroll
    for (int i = 0; i < 16; i++)
        #pragma unroll
        for (int e = 0; e < 4; e++) acc[i][e] = 0.f;

    int nch = (K / SPLITK) / BK;

    auto issue = [&](int c) {
        uint32_t sb = smb + (uint32_t)(c & 1) * STAGE_B;
        int kb = kb0 + c * BK;
        #pragma unroll
        for (int rep = 0; rep < REPS; rep++) {
            int cid = tid + rep * 256;
            int row = cid >> CHSH, ch = cid & ((1 << CHSH) - 1);
            uint32_t doff = (uint32_t)(row * ROWB + ch * 16);
            size_t ga = (size_t)(bm + row) * K + kb + ch * 8;
            cp16(sb + doff, Ahi + ga);
            if (ALO) cp16(sb + PLANE + doff, Alo + ga);
            int br = bn + row; if (br >= N) br = N - 1;
            size_t gb = (size_t)br * K + kb + ch * 8;
            cp16(sb + APL * PLANE + doff, Bhi + gb);
            if (!GHOST) cp16(sb + (APL + 1) * PLANE + doff, Blo + gb);
        }
        CP_COMMIT();
    };

    issue(0);
    if (nch > 1) issue(1);

    uint32_t aoffL = (uint32_t)((wm + (lane & 15)) * ROWB + ((lane >> 4) << 4));
    uint32_t boffL = (uint32_t)((wn + (lane & 7) + ((lane >> 4) << 3)) * ROWB
                                + (((lane >> 3) & 1) << 4));

    for (int c = 0; c < nch; c++) {
        if (c + 1 < nch) CP_WAIT1(); else CP_WAIT0();
        __syncthreads();

        uint32_t sb = smb + (uint32_t)(c & 1) * STAGE_B;
        #pragma unroll
        for (int ks = 0; ks < KS_N; ks++) {
            uint32_t ao = sb + aoffL + ks * 32;
            uint32_t bo = sb + APL * PLANE + boffL + ks * 32;
            unsigned ah[4][4], al[4][4], bh[4][2], bl[4][2];
            #pragma unroll
            for (int i = 0; i < 4; i++) {
                LDSM4(ah[i][0], ah[i][1], ah[i][2], ah[i][3], ao + i * 16 * ROWB);
                if (ALO)
                    LDSM4(al[i][0], al[i][1], al[i][2], al[i][3], ao + PLANE + i * 16 * ROWB);
            }
            #pragma unroll
            for (int j2 = 0; j2 < 2; j2++) {
                unsigned r0, r1, r2, r3;
                LDSM4(r0, r1, r2, r3, bo + j2 * 16 * ROWB);
                bh[j2 * 2][0] = r0; bh[j2 * 2][1] = r1;
                bh[j2 * 2 + 1][0] = r2; bh[j2 * 2 + 1][1] = r3;
                if (!GHOST) {
                    LDSM4(r0, r1, r2, r3, bo + PLANE + j2 * 16 * ROWB);
                    bl[j2 * 2][0] = r0; bl[j2 * 2][1] = r1;
                    bl[j2 * 2 + 1][0] = r2; bl[j2 * 2 + 1][1] = r3;
                }
            }
            #pragma unroll
            for (int i = 0; i < 4; i++)
                #pragma unroll
                for (int j = 0; j < 4; j++) {
                    float* a4 = acc[i * 4 + j];
                    MMA16816(a4, ah[i][0], ah[i][1], ah[i][2], ah[i][3], bh[j][0], bh[j][1]);
                    if (ALO)
                        MMA16816(a4, al[i][0], al[i][1], al[i][2], al[i][3], bh[j][0], bh[j][1]);
                    if (!GHOST)
                        MMA16816(a4, ah[i][0], ah[i][1], ah[i][2], ah[i][3], bl[j][0], bl[j][1]);
                }
        }
        __syncthreads();
        if (c + 2 < nch) issue(c + 2);
    }

    // ---- epilogue ----
    if (SPLITK > 1) {
        float* Cp = C + (size_t)blockIdx.z * M * N;
        #pragma unroll
        for (int i = 0; i < 4; i++) {
            int mA = bm + wm + i * 16 + grp;
            #pragma unroll
            for (int j = 0; j < 4; j++) {
                int n0 = bn + wn + j * 8 + 2 * tg;
                #pragma unroll
                for (int e = 0; e < 4; e++) {
                    int m = mA + ((e >= 2) ? 8 : 0);
                    int n = n0 + (e & 1);
                    Cp[(size_t)m * N + n] = acc[i * 4 + j][e];
                }
            }
        }
        return;
    }

    float c0f = 0.f, c1f = 0.f;
    if (GHOST) {
        float L0 = __ldg(lutp), L255 = __ldg(lutp + 255);
        c0f = L0;
        c1f = (L255 - L0) * (1.0f / 255.0f);
    }
    #pragma unroll
    for (int i = 0; i < 4; i++) {
        int mA = bm + wm + i * 16 + grp;
        float s0a = 0.f, s0b = 0.f;
        if (GHOST) { s0a = S0[mA]; s0b = S0[mA + 8]; }
        float rsA = 0.f, rsB = 0.f;
        #pragma unroll
        for (int j = 0; j < 4; j++) {
            int n0 = bn + wn + j * 8 + 2 * tg;
            #pragma unroll
            for (int e = 0; e < 4; e++) {
                int m = mA + ((e >= 2) ? 8 : 0);
                int n = n0 + (e & 1);
                if (n < N) {
                    float t = acc[i * 4 + j][e];
                    if (GHOST) t = (c1f * t + c0f * ((e >= 2) ? s0b : s0a)) * scale[n];
                    if (BIAS)  t += bias[n];
                    if (GELU)  t = gelu_tanh(t);
                    if (RESID) t += resid[(size_t)m * N + n];
                    if (ROWSUM) { if (e >= 2) rsB += t; else rsA += t; }
                    if (OUTSPLIT) {
                        __half hh, ll; split1(t, hh, ll);
                        Ohi[(size_t)m * N + n] = hh;
                        Olo[(size_t)m * N + n] = ll;
                    } else {
                        C[(size_t)m * N + n] = t;
                    }
                }
            }
        }
        if (ROWSUM) {
            rsA += __shfl_xor_sync(0xffffffffu, rsA, 1);
            rsA += __shfl_xor_sync(0xffffffffu, rsA, 2);
            rsB += __shfl_xor_sync(0xffffffffu, rsB, 1);
            rsB += __shfl_xor_sync(0xffffffffu, rsB, 2);
            if (tg == 0) {
                atomicAdd(s0out + mA, rsA);
                atomicAdd(s0out + mA + 8, rsB);
            }
        }
    }
}

// ---------------- launch ----------------
extern "C" void kernel_launch(void* const* d_in, const int* in_sizes, int n_in,
                              void* d_out, int out_size) {
    const float* lut        = (const float*)d_in[0];
    const float* tok_emb    = (const float*)d_in[1];
    const float* pos_emb    = (const float*)d_in[2];
    const float* ln1_g      = (const float*)d_in[3];
    const float* ln1_b      = (const float*)d_in[4];
    const float* in_w       = (const float*)d_in[5];
    const float* in_b       = (const float*)d_in[6];
    const float* out_w      = (const float*)d_in[7];
    const float* out_b      = (const float*)d_in[8];
    const float* ln2_g      = (const float*)d_in[9];
    const float* ln2_b      = (const float*)d_in[10];
    const float* mlp1_scale = (const float*)d_in[11];
    const float* mlp2_scale = (const float*)d_in[12];
    const float* lnf_g      = (const float*)d_in[13];
    const float* lnf_b      = (const float*)d_in[14];
    const float* head_scale = (const float*)d_in[15];
    const int*   mlp1_idx   = (const int*)d_in[16];
    const int*   mlp2_idx   = (const int*)d_in[17];
    const int*   head_idx   = (const int*)d_in[18];
    const int*   idx        = (const int*)d_in[19];
    float* out = (float*)d_out;

    float *x, *qkv, *part, *s0_ln, *s0_mlp;
    __half *ln_hi, *ln_lo, *att_hi, *att_lo, *mlp_hi, *mlp_lo;
    __half *wq_hi, *wq_lo, *wp_hi, *wp_lo, *w1_i, *w2_i, *wh_i;
    cudaGetSymbolAddress((void**)&x,      g_x);
    cudaGetSymbolAddress((void**)&qkv,    g_qkv);
    cudaGetSymbolAddress((void**)&part,   g_part);
    cudaGetSymbolAddress((void**)&s0_ln,  g_s0_ln);
    cudaGetSymbolAddress((void**)&s0_mlp, g_s0_mlp);
    cudaGetSymbolAddress((void**)&ln_hi,  g_ln_hi);
    cudaGetSymbolAddress((void**)&ln_lo,  g_ln_lo);
    cudaGetSymbolAddress((void**)&att_hi, g_att_hi);
    cudaGetSymbolAddress((void**)&att_lo, g_att_lo);
    cudaGetSymbolAddress((void**)&mlp_hi, g_mlp_hi);
    cudaGetSymbolAddress((void**)&mlp_lo, g_mlp_lo);
    cudaGetSymbolAddress((void**)&wq_hi,  w_qkv_hi);
    cudaGetSymbolAddress((void**)&wq_lo,  w_qkv_lo);
    cudaGetSymbolAddress((void**)&wp_hi,  w_proj_hi);
    cudaGetSymbolAddress((void**)&wp_lo,  w_proj_lo);
    cudaGetSymbolAddress((void**)&w1_i,   w_mlp1_i);
    cudaGetSymbolAddress((void**)&w2_i,   w_mlp2_i);
    cudaGetSymbolAddress((void**)&wh_i,   w_head_i);

    static int attr_done = 0;
    if (!attr_done) {
        cudaFuncSetAttribute(hgemm<0,1,1,0,0,0,1,0>, cudaFuncAttributeMaxDynamicSharedMemorySize, SM_DENSE);
        cudaFuncSetAttribute(hgemm<0,1,0,0,0,0,3,0>, cudaFuncAttributeMaxDynamicSharedMemorySize, SM_DENSE);
        cudaFuncSetAttribute(hgemm<1,1,0,1,0,1,1,1>, cudaFuncAttributeMaxDynamicSharedMemorySize, SM_GHOST);
        cudaFuncSetAttribute(hgemm<1,1,0,0,0,0,3,0>, cudaFuncAttributeMaxDynamicSharedMemorySize, SM_GHOST);
        cudaFuncSetAttribute(hgemm<1,0,0,0,0,0,1,0>, cudaFuncAttributeMaxDynamicSharedMemorySize, SM_HEAD);
        cudaFuncSetAttribute(flash_attn,             cudaFuncAttributeMaxDynamicSharedMemorySize, SM_ATTN);
        attr_done = 1;
    }

    conv_all<<<NB0 + NB1 + NB2 + NB3 + NB4, 256>>>(
        in_w, out_w, mlp1_idx, mlp2_idx, head_idx,
        wq_hi, wq_lo, wp_hi, wp_lo, w1_i, w2_i, wh_i);

    embed_kernel<<<BT, 256>>>(idx, tok_emb, pos_emb, x);

    // layer 0 ln1 (subsequent ln1 fused into mlp2 combine)
    ln_kernel<<<BT, 256>>>(x, ln1_g, ln1_b, ln_hi, ln_lo, s0_ln);

    for (int l = 0; l < NL; l++) {
        {
            dim3 grid(BT / 128, QKVW / 128);          // 16 x 18
            hgemm<0,1,1,0,0,0,1,0><<<grid, 256, SM_DENSE>>>(
                ln_hi, ln_lo,
                wq_hi + (size_t)l * QKVW * DIMN, wq_lo + (size_t)l * QKVW * DIMN,
                in_b + (size_t)l * QKVW, nullptr, nullptr, nullptr, nullptr,
                qkv, nullptr, nullptr, nullptr, BT, QKVW, DIMN);
        }
        {
            dim3 grid(SEQ / QT, NH, BATCH);
            flash_attn<<<grid, 256, SM_ATTN>>>(qkv, att_hi, att_lo);
        }
        {
            // proj: split-K=3 partials; fused combine + ln2 (+ zero s0_mlp)
            dim3 grid(BT / 128, DIMN / 128, 3);       // 288 CTAs = 1 wave
            hgemm<0,1,0,0,0,0,3,0><<<grid, 256, SM_DENSE>>>(
                att_hi, att_lo,
                wp_hi + (size_t)l * DIMN * DIMN, wp_lo + (size_t)l * DIMN * DIMN,
                nullptr, nullptr, nullptr, nullptr, nullptr,
                part, nullptr, nullptr, nullptr, BT, DIMN, DIMN);
            combine_ln<3,0><<<BT, 192>>>(part, out_b + (size_t)l * DIMN,
                                         nullptr, nullptr, nullptr,
                                         ln2_g + (size_t)l * DIMN, ln2_b + (size_t)l * DIMN,
                                         x, ln_hi, ln_lo, s0_ln, s0_mlp);
        }
        {
            // mlp1: rowsum fused into epilogue via atomics (s0_mlp pre-zeroed)
            dim3 grid(BT / 128, HID / 128);           // 16 x 24
            hgemm<1,1,0,1,0,1,1,1><<<grid, 256, SM_GHOST>>>(
                ln_hi, ln_lo,
                w1_i + (size_t)l * HID * DIMN, nullptr,
                nullptr, mlp1_scale + (size_t)l * HID, s0_ln, lut, nullptr,
                nullptr, mlp_hi, mlp_lo, s0_mlp, BT, HID, DIMN);
        }
        {
            // mlp2: split-K=3 partials; fused combine + next ln1 (or lnf)
            dim3 grid(BT / 128, DIMN / 128, 3);       // 288 CTAs = 1 wave
            hgemm<1,1,0,0,0,0,3,0><<<grid, 256, SM_GHOST>>>(
                mlp_hi, mlp_lo,
                w2_i + (size_t)l * DIMN * HID, nullptr,
                nullptr, nullptr, nullptr, nullptr, nullptr,
                part, nullptr, nullptr, nullptr, BT, DIMN, HID);
            const float* gn = (l + 1 < NL) ? (ln1_g + (size_t)(l + 1) * DIMN) : lnf_g;
            const float* bn = (l + 1 < NL) ? (ln1_b + (size_t)(l + 1) * DIMN) : lnf_b;
            combine_ln<3,1><<<BT, 192>>>(part, nullptr,
                                         mlp2_scale + (size_t)l * DIMN, s0_mlp, lut,
                                         gn, bn, x, ln_hi, ln_lo, s0_ln, nullptr);
        }
    }

    {
        dim3 grid(BT / 128, (VOCAB + 127) / 128);     // 16 x 393
        hgemm<1,0,0,0,0,0,1,0><<<grid, 256, SM_HEAD>>>(
            ln_hi, nullptr, wh_i, nullptr,
            nullptr, head_scale, s0_ln, lut, nullptr,
            out, nullptr, nullptr, nullptr, BT, VOCAB, DIMN);
    }
}